// round 10
// baseline (speedup 1.0000x reference)
#include <cuda_runtime.h>
#include <cuda_bf16.h>
#include <math.h>
#include <stdint.h>

// Problem dims (fixed)
#define Bv   16
#define Cv   256
#define Hv   32
#define Wv   32
#define Nv   16384          // B*H*W tokens
#define Ev   16384          // n_e codes
#define S0   4194304        // B*C*H*W = start of scalar outputs

// GEMM tiling
#define KBIG 768            // [hi | lo | hi] x [hi | hi | lo]
#define BM   128
#define BN   128
#define BK   32
#define NKT  (KBIG / BK)    // 24 k-iterations
#define ROWB 80             // padded smem row stride in bytes
#define STG  (2 * BM * ROWB)        // 20480 bytes per stage (A + B)
#define SM_TOTAL (3 * STG)          // 61440

#define CAND_EPS 1e-2f
#define MAXCAND 32
#define RB 128              // rows per block in fused row/col pass
#define ROWCOL_SMEM (2 * Ev * 4)    // 131072

// ---------------- device scratch (static, no allocs) ----------------
__device__ float              g_zf[(size_t)Nv * Cv];
__device__ float              g_cn[Nv];
__device__ float              g_emb[(size_t)Ev * Cv];
__device__ float              g_sk[Ev];
__device__ __align__(256) __nv_bfloat16 g_abig[(size_t)Nv * KBIG];
__device__ __align__(256) __nv_bfloat16 g_bbig[(size_t)Ev * KBIG];
__device__ float              g_t[(size_t)Nv * Ev];   // 1 GiB
__device__ unsigned long long g_rowmax[Nv];
__device__ int                g_idx[Nv];
__device__ float              g_avgp[Ev];
__device__ int                g_q[Bv];
__device__ float              g_acc[8];

__device__ __forceinline__ unsigned int ford(float f) {
    unsigned int u = __float_as_uint(f);
    return (u & 0x80000000u) ? ~u : (u | 0x80000000u);
}

// ---------------- PTX helpers (base-target only) ----------------
__device__ __forceinline__ uint32_t smem_u32(const void* p) {
    uint32_t a;
    asm("{ .reg .u64 t; cvta.to.shared.u64 t, %1; cvt.u32.u64 %0, t; }" : "=r"(a) : "l"(p));
    return a;
}
__device__ __forceinline__ void cp16(uint32_t dst, const void* src) {
    asm volatile("cp.async.cg.shared.global [%0], [%1], 16;" :: "r"(dst), "l"(src) : "memory");
}
__device__ __forceinline__ void cp_commit() {
    asm volatile("cp.async.commit_group;" ::: "memory");
}
template <int N>
__device__ __forceinline__ void cp_wait() {
    asm volatile("cp.async.wait_group %0;" :: "n"(N) : "memory");
}
__device__ __forceinline__ void ldmx4(uint32_t& r0, uint32_t& r1, uint32_t& r2, uint32_t& r3,
                                      uint32_t addr) {
    asm volatile("ldmatrix.sync.aligned.m8n8.x4.shared.b16 {%0,%1,%2,%3}, [%4];"
                 : "=r"(r0), "=r"(r1), "=r"(r2), "=r"(r3) : "r"(addr));
}
__device__ __forceinline__ void hmma(float& c0, float& c1, float& c2, float& c3,
                                     uint32_t a0, uint32_t a1, uint32_t a2, uint32_t a3,
                                     uint32_t b0, uint32_t b1) {
    asm volatile(
        "mma.sync.aligned.m16n8k16.row.col.f32.bf16.bf16.f32 "
        "{%0,%1,%2,%3}, {%4,%5,%6,%7}, {%8,%9}, {%0,%1,%2,%3};"
        : "+f"(c0), "+f"(c1), "+f"(c2), "+f"(c3)
        : "r"(a0), "r"(a1), "r"(a2), "r"(a3), "r"(b0), "r"(b1));
}

// ---------------- init ----------------
__global__ void k_init(const void* qraw) {
    int i = blockIdx.x * blockDim.x + threadIdx.x;
    if (i < Ev) g_avgp[i] = 0.0f;
    if (i < Nv) g_rowmax[i] = 0ull;
    if (i == 0) {
        const unsigned int* w32 = (const unsigned int*)qraw;
        bool is64 = true;
        for (int b = 0; b < 8; b++) if (w32[2 * b + 1] != 0u) is64 = false;
        int s = 0;
        for (int b = 0; b < Bv; b++) {
            int q = is64 ? (int)w32[2 * b] : (int)((const int*)qraw)[b];
            g_q[b] = q;
            s += q + 1;
        }
        for (int j = 0; j < 8; j++) g_acc[j] = 0.0f;
        g_acc[1] = (float)s;
    }
}

// ---------------- normalize z + emit bf16 split ----------------
__global__ __launch_bounds__(256) void k_norm_z(const float* __restrict__ z) {
    __shared__ float sm[Cv][Wv + 1];
    __shared__ float sinv[Wv];
    int bh = blockIdx.x;
    int tid = threadIdx.x;
    const float* zp = z + (size_t)(bh >> 5) * Cv * (Hv * Wv) + (size_t)(bh & 31) * Wv;
    for (int it = 0; it < 32; ++it) {
        int l = it * 256 + tid;
        int c = l >> 5, w = l & 31;
        sm[c][w] = zp[(size_t)c * (Hv * Wv) + w];
    }
    __syncthreads();
    int w = tid >> 3, part = tid & 7;
    float s = 0.0f;
    for (int c = part; c < Cv; c += 8) { float v = sm[c][w]; s += v * v; }
    s += __shfl_xor_sync(~0u, s, 1);
    s += __shfl_xor_sync(~0u, s, 2);
    s += __shfl_xor_sync(~0u, s, 4);
    if (part == 0) {
        float inv = 1.0f / fmaxf(sqrtf(s), 1e-12f);
        sinv[w] = inv;
        g_cn[bh * 32 + w] = s * inv * inv;
    }
    __syncthreads();
    for (int w2 = 0; w2 < 32; ++w2) {
        int n = bh * 32 + w2;
        float v = sm[tid][w2] * sinv[w2];
        g_zf[(size_t)n * Cv + tid] = v;
        __nv_bfloat16 h = __float2bfloat16(v);
        __nv_bfloat16 l = __float2bfloat16(v - __bfloat162float(h));
        size_t base = (size_t)n * KBIG;
        g_abig[base + tid]       = h;
        g_abig[base + 256 + tid] = l;
        g_abig[base + 512 + tid] = h;
    }
}

// ---------------- normalize embedding + emit bf16 split ----------------
__global__ __launch_bounds__(256) void k_norm_emb(const float* __restrict__ e) {
    int k = blockIdx.x, tid = threadIdx.x;
    float v = e[(size_t)k * Cv + tid];
    float s = v * v;
    for (int o = 16; o; o >>= 1) s += __shfl_xor_sync(~0u, s, o);
    __shared__ float ws[8];
    if ((tid & 31) == 0) ws[tid >> 5] = s;
    __syncthreads();
    if (tid < 8) {
        float t = ws[tid];
        for (int o = 4; o; o >>= 1) t += __shfl_xor_sync(0xffu, t, o);
        if (tid == 0) ws[0] = t;
    }
    __syncthreads();
    float tot = ws[0];
    float inv = 1.0f / fmaxf(sqrtf(tot), 1e-12f);
    float vn = v * inv;
    g_emb[(size_t)k * Cv + tid] = vn;
    if (tid == 0) g_sk[k] = tot * inv * inv;
    __nv_bfloat16 h = __float2bfloat16(vn);
    __nv_bfloat16 l = __float2bfloat16(vn - __bfloat162float(h));
    size_t base = (size_t)k * KBIG;
    g_bbig[base + tid]       = h;
    g_bbig[base + 256 + tid] = h;
    g_bbig[base + 512 + tid] = l;
}

// ---------------- HMMA GEMM (ldmatrix): t = 200*G - 100*s_k, fused row argmax ----------------
__device__ __forceinline__ void load_stage(uint32_t sbase, int s, const char* Ab,
                                           const char* Bb, int kt, int tid) {
    uint32_t base = sbase + s * STG;
    const char* Asrc = Ab + kt * (BK * 2);
#pragma unroll
    for (int i = 0; i < 2; i++) {
        int u = tid + i * 256;
        int r = u >> 2, c = u & 3;
        cp16(base + r * ROWB + c * 16, Asrc + (size_t)r * (KBIG * 2) + c * 16);
    }
    uint32_t bbase = base + BM * ROWB;
    const char* Bsrc = Bb + kt * (BK * 2);
#pragma unroll
    for (int i = 0; i < 2; i++) {
        int u = tid + i * 256;
        int r = u >> 2, c = u & 3;
        cp16(bbase + r * ROWB + c * 16, Bsrc + (size_t)r * (KBIG * 2) + c * 16);
    }
}

__global__ void __launch_bounds__(256) k_mma() {
    extern __shared__ char smem[];
    uint32_t sbase = smem_u32(smem);
    int tid = threadIdx.x, wid = tid >> 5, lane = tid & 31;
    int g = lane >> 2, tig = lane & 3;
    int warpM = wid >> 2, warpN = wid & 3;          // 2 x 4
    int bm = blockIdx.y * BM, bn = blockIdx.x * BN;

    const char* Ab = (const char*)g_abig + (size_t)bm * (KBIG * 2);
    const char* Bb = (const char*)g_bbig + (size_t)bn * (KBIG * 2);

    // ldmatrix per-lane offsets
    int aoff = ((((lane >> 3) & 1) * 8 + (lane & 7)) * ROWB) + ((lane >> 4) * 16);
    int boff = ((((lane >> 4) & 1) * 8 + (lane & 7)) * ROWB) + (((lane >> 3) & 1) * 16);
    uint32_t abase = sbase + (warpM * 64) * ROWB + aoff;
    uint32_t bbase = sbase + BM * ROWB + (warpN * 32) * ROWB + boff;

    float acc[4][4][4];
#pragma unroll
    for (int mi = 0; mi < 4; mi++)
#pragma unroll
        for (int ni = 0; ni < 4; ni++)
#pragma unroll
            for (int r = 0; r < 4; r++) acc[mi][ni][r] = 0.0f;

    load_stage(sbase, 0, Ab, Bb, 0, tid); cp_commit();
    load_stage(sbase, 1, Ab, Bb, 1, tid); cp_commit();

    for (int kt = 0; kt < NKT; kt++) {
        cp_wait<1>();
        __syncthreads();
        if (kt + 2 < NKT) load_stage(sbase, (kt + 2) % 3, Ab, Bb, kt + 2, tid);
        cp_commit();

        uint32_t stg = (uint32_t)((kt % 3) * STG);
#pragma unroll
        for (int k16 = 0; k16 < 2; k16++) {
            uint32_t koff = k16 * 32;
            uint32_t Ar[4][4], Br[4][2];
#pragma unroll
            for (int mi = 0; mi < 4; mi++)
                ldmx4(Ar[mi][0], Ar[mi][1], Ar[mi][2], Ar[mi][3],
                      abase + stg + mi * 16 * ROWB + koff);
#pragma unroll
            for (int nip = 0; nip < 2; nip++)
                ldmx4(Br[2 * nip][0], Br[2 * nip][1], Br[2 * nip + 1][0], Br[2 * nip + 1][1],
                      bbase + stg + nip * 16 * ROWB + koff);
#pragma unroll
            for (int mi = 0; mi < 4; mi++)
#pragma unroll
                for (int ni = 0; ni < 4; ni++)
                    hmma(acc[mi][ni][0], acc[mi][ni][1], acc[mi][ni][2], acc[mi][ni][3],
                         Ar[mi][0], Ar[mi][1], Ar[mi][2], Ar[mi][3],
                         Br[ni][0], Br[ni][1]);
        }
        __syncthreads();
    }

    // epilogue
    int rowb = bm + warpM * 64;
    int colb = bn + warpN * 32;
    float skv[4][2];
#pragma unroll
    for (int ni = 0; ni < 4; ni++) {
        int c0 = colb + ni * 8 + 2 * tig;
        skv[ni][0] = __ldg(&g_sk[c0]);
        skv[ni][1] = __ldg(&g_sk[c0 + 1]);
    }
    float rv[4][2]; int rc[4][2];
#pragma unroll
    for (int mi = 0; mi < 4; mi++) { rv[mi][0] = rv[mi][1] = -3.4e38f; rc[mi][0] = rc[mi][1] = 0x7fffffff; }

#pragma unroll
    for (int mi = 0; mi < 4; mi++) {
        int r0 = rowb + mi * 16 + g;
        float* p0 = g_t + (size_t)r0 * Ev;
        float* p1 = g_t + (size_t)(r0 + 8) * Ev;
#pragma unroll
        for (int ni = 0; ni < 4; ni++) {
            int c0 = colb + ni * 8 + 2 * tig;
            float t00 = 200.0f * acc[mi][ni][0] - 100.0f * skv[ni][0];
            float t01 = 200.0f * acc[mi][ni][1] - 100.0f * skv[ni][1];
            float t10 = 200.0f * acc[mi][ni][2] - 100.0f * skv[ni][0];
            float t11 = 200.0f * acc[mi][ni][3] - 100.0f * skv[ni][1];
            *(float2*)(p0 + c0) = make_float2(t00, t01);
            *(float2*)(p1 + c0) = make_float2(t10, t11);
            if (t00 > rv[mi][0]) { rv[mi][0] = t00; rc[mi][0] = c0; }
            if (t01 > rv[mi][0]) { rv[mi][0] = t01; rc[mi][0] = c0 + 1; }
            if (t10 > rv[mi][1]) { rv[mi][1] = t10; rc[mi][1] = c0; }
            if (t11 > rv[mi][1]) { rv[mi][1] = t11; rc[mi][1] = c0 + 1; }
        }
    }
#pragma unroll
    for (int mi = 0; mi < 4; mi++)
#pragma unroll
        for (int h = 0; h < 2; h++) {
#pragma unroll
            for (int o = 1; o < 4; o <<= 1) {
                float ov = __shfl_xor_sync(~0u, rv[mi][h], o);
                int   oc = __shfl_xor_sync(~0u, rc[mi][h], o);
                if (ov > rv[mi][h] || (ov == rv[mi][h] && oc < rc[mi][h])) {
                    rv[mi][h] = ov; rc[mi][h] = oc;
                }
            }
            if (tig == 0) {
                int row = rowb + mi * 16 + g + h * 8;
                unsigned long long key =
                    ((unsigned long long)ford(rv[mi][h]) << 32) |
                    (unsigned long long)(0xFFFFFFFFu - (unsigned)rc[mi][h]);
                atomicMax(&g_rowmax[row], key);
            }
        }
}

// ---------------- fused row+col pass: Z/U/idx/dmin + avg_probs, one t read ----------------
__global__ __launch_bounds__(256) void k_rowcol() {
    extern __shared__ float sh[];       // e[Ev], colacc[Ev]
    float* e = sh;
    float* colacc = sh + Ev;
    float4* e4 = (float4*)e;
    float4* ca4 = (float4*)colacc;
    int tid = threadIdx.x;

    __shared__ float wz[8], wu[8];
    __shared__ int s_cand[MAXCAND];
    __shared__ int s_cnt;
    __shared__ int s_bidx;
    __shared__ float s_bt;
    __shared__ float s_r;
    __shared__ float blk_ent, blk_dmin;
    if (tid == 0) { blk_ent = 0.0f; blk_dmin = 0.0f; }
    for (int i = tid; i < Ev; i += 256) colacc[i] = 0.0f;

    int n0 = blockIdx.x * RB;
    for (int rr = 0; rr < RB; rr++) {
        int n = n0 + rr;
        unsigned long long key = g_rowmax[n];
        unsigned int o = (unsigned int)(key >> 32);
        unsigned int ub = (o & 0x80000000u) ? (o & 0x7FFFFFFFu) : ~o;
        float m = __uint_as_float(ub);
        int kidx = (int)(0xFFFFFFFFu - (unsigned int)(key & 0xFFFFFFFFull));
        if (tid == 0) { s_cnt = 0; s_bidx = kidx; s_bt = m; }
        __syncthreads();

        float thr = m - CAND_EPS;
        const float4* row = (const float4*)(g_t + (size_t)n * Ev);
        float Z = 0.0f, U = 0.0f;
#pragma unroll 4
        for (int i = tid; i < Ev / 4; i += 256) {
            float4 v = row[i];
            float u0 = v.x - m, u1 = v.y - m, u2 = v.z - m, u3 = v.w - m;
            float e0 = __expf(u0), e1 = __expf(u1), e2 = __expf(u2), e3 = __expf(u3);
            e4[i] = make_float4(e0, e1, e2, e3);
            Z += e0 + e1 + e2 + e3;
            U += e0 * u0 + e1 * u1 + e2 * u2 + e3 * u3;
            if (v.x > thr) { int p = atomicAdd(&s_cnt, 1); if (p < MAXCAND) s_cand[p] = 4 * i; }
            if (v.y > thr) { int p = atomicAdd(&s_cnt, 1); if (p < MAXCAND) s_cand[p] = 4 * i + 1; }
            if (v.z > thr) { int p = atomicAdd(&s_cnt, 1); if (p < MAXCAND) s_cand[p] = 4 * i + 2; }
            if (v.w > thr) { int p = atomicAdd(&s_cnt, 1); if (p < MAXCAND) s_cand[p] = 4 * i + 3; }
        }
        for (int off = 16; off; off >>= 1) {
            Z += __shfl_xor_sync(~0u, Z, off);
            U += __shfl_xor_sync(~0u, U, off);
        }
        if ((tid & 31) == 0) { wz[tid >> 5] = Z; wu[tid >> 5] = U; }
        __syncthreads();

        // exact refinement on ambiguity (warp 0), R4-identical sequential-k fp32
        int nc = min(s_cnt, MAXCAND);
        if (nc >= 2 && tid < 32) {
            float bt = -3.4e38f; int bc = 0x7fffffff;
            if (tid < nc) {
                int k = s_cand[tid];
                const float* ap = g_zf + (size_t)n * Cv;
                const float* bp = g_emb + (size_t)k * Cv;
                float dot = 0.0f;
#pragma unroll 8
                for (int c = 0; c < Cv; c++) dot = fmaf(__ldg(ap + c), __ldg(bp + c), dot);
                bt = 200.0f * dot - 100.0f * __ldg(&g_sk[k]);
                bc = k;
            }
#pragma unroll
            for (int off2 = 1; off2 < 32; off2 <<= 1) {
                float ov = __shfl_xor_sync(~0u, bt, off2);
                int   oc = __shfl_xor_sync(~0u, bc, off2);
                if (ov > bt || (ov == bt && oc < bc)) { bt = ov; bc = oc; }
            }
            if (tid == 0) { s_bidx = bc; s_bt = bt; }
        }
        __syncthreads();

        if (tid == 0) {
            float Zt = 0.0f, Ut = 0.0f;
            for (int w = 0; w < 8; w++) { Zt += wz[w]; Ut += wu[w]; }
            s_r = 1.0f / Zt;
            blk_ent += __logf(Zt) - Ut / Zt;
            g_idx[n] = s_bidx;
            float dmin = g_cn[n] - 0.01f * s_bt;
            int b = n >> 10, w = n & 31;
            if (w <= g_q[b]) blk_dmin += dmin;
        }
        __syncthreads();

        float r = s_r;
#pragma unroll 4
        for (int i = tid; i < Ev / 4; i += 256) {
            float4 ee = e4[i];
            float4 ca = ca4[i];
            ca.x += ee.x * r; ca.y += ee.y * r; ca.z += ee.z * r; ca.w += ee.w * r;
            ca4[i] = ca;
        }
        __syncthreads();
    }

    for (int i = tid; i < Ev; i += 256) atomicAdd(&g_avgp[i], colacc[i]);
    if (tid == 0) {
        atomicAdd(&g_acc[2], blk_ent);
        atomicAdd(&g_acc[0], blk_dmin);
    }
}

// ---------------- avg entropy ----------------
__global__ __launch_bounds__(256) void k_avgent() {
    int k = blockIdx.x * 256 + threadIdx.x;
    float ap = g_avgp[k] * (1.0f / (float)Nv);
    float v = -ap * __logf(ap + 1e-5f);
    for (int o = 16; o; o >>= 1) v += __shfl_xor_sync(~0u, v, o);
    __shared__ float ws[8];
    if ((threadIdx.x & 31) == 0) ws[threadIdx.x >> 5] = v;
    __syncthreads();
    if (threadIdx.x == 0) {
        float t = 0.0f;
        for (int w = 0; w < 8; w++) t += ws[w];
        atomicAdd(&g_acc[3], t);
    }
}

// ---------------- dead code rate ----------------
__global__ void k_dead() {
    int j = threadIdx.x;
    int v = g_idx[j];
    int same = 1;
    for (int b = 1; b < Bv; b++) same &= (g_idx[b * 1024 + j] == v);
    for (int o = 16; o; o >>= 1) same += __shfl_xor_sync(~0u, same, o);
    __shared__ int ws[32];
    if ((j & 31) == 0) ws[j >> 5] = same;
    __syncthreads();
    if (j < 32) {
        int t = ws[j];
        for (int o = 16; o; o >>= 1) t += __shfl_xor_sync(~0u, t, o);
        if (j == 0) g_acc[4] = (float)t;
    }
}

// ---------------- z_q output ----------------
__global__ __launch_bounds__(256) void k_output(float* __restrict__ out) {
    __shared__ float sm[Cv][Wv + 1];
    int bh = blockIdx.x, tid = threadIdx.x;
    for (int w = 0; w < 32; ++w) {
        int n = bh * 32 + w;
        int k = g_idx[n];
        float zf = g_zf[(size_t)n * Cv + tid];
        float e  = g_emb[(size_t)k * Cv + tid];
        sm[tid][w] = zf + (e - zf);
    }
    __syncthreads();
    float* op = out + (size_t)(bh >> 5) * Cv * (Hv * Wv) + (size_t)(bh & 31) * Wv;
    for (int it = 0; it < 32; ++it) {
        int l = it * 256 + tid;
        int c = l >> 5, w = l & 31;
        op[(size_t)c * (Hv * Wv) + w] = sm[c][w];
    }
}

// ---------------- scalars + idx ----------------
__global__ void k_finalize(float* __restrict__ out, int out_size) {
    int i = blockIdx.x * blockDim.x + threadIdx.x;
    if (i < Nv && (S0 + 4 + i) < out_size) out[S0 + 4 + i] = (float)g_idx[i];
    if (i == 0 && (S0 + 3) < out_size) {
        float denom = g_acc[1];
        float vq = g_acc[0] / (256.0f * denom);
        out[S0 + 0] = vq;
        out[S0 + 1] = 0.25f * vq;
        float sample = g_acc[2] * (1.0f / (float)Nv);
        out[S0 + 2] = 0.1f * (sample - g_acc[3]);
        out[S0 + 3] = g_acc[4] * (1.0f / 1024.0f);
    }
}

extern "C" void kernel_launch(void* const* d_in, const int* in_sizes, int n_in,
                              void* d_out, int out_size) {
    const float* z   = (const float*)d_in[0];
    const float* emb = (const float*)d_in[1];
    const void*  q   = d_in[2];
    float* out = (float*)d_out;

    cudaFuncSetAttribute(k_mma, cudaFuncAttributeMaxDynamicSharedMemorySize, SM_TOTAL);
    cudaFuncSetAttribute(k_rowcol, cudaFuncAttributeMaxDynamicSharedMemorySize, ROWCOL_SMEM);

    k_init<<<64, 256>>>(q);
    k_norm_z<<<Bv * Hv, 256>>>(z);
    k_norm_emb<<<Ev, 256>>>(emb);
    dim3 gg(Ev / BN, Nv / BM);    // 128 x 128 tiles
    k_mma<<<gg, 256, SM_TOTAL>>>();
    k_rowcol<<<Nv / RB, 256, ROWCOL_SMEM>>>();
    k_avgent<<<Ev / 256, 256>>>();
    k_dead<<<1, 1024>>>();
    k_output<<<Bv * Hv, 256>>>(out);
    k_finalize<<<64, 256>>>(out, out_size);
}

// round 12
// speedup vs baseline: 1.3675x; 1.3675x over previous
#include <cuda_runtime.h>
#include <cuda_bf16.h>
#include <math.h>
#include <stdint.h>

// Problem dims (fixed)
#define Bv   16
#define Cv   256
#define Hv   32
#define Wv   32
#define Nv   16384          // B*H*W tokens
#define Ev   16384          // n_e codes
#define S0   4194304        // B*C*H*W = start of scalar outputs

// GEMM tiling
#define KBIG 768            // [hi | lo | hi] x [hi | hi | lo]
#define BM   128
#define BN   128
#define BK   32
#define NKT  (KBIG / BK)    // 24 k-iterations
#define ROWB 80             // padded smem row stride in bytes
#define STG  (2 * BM * ROWB)        // 20480 bytes per stage (A + B)
#define SM_TOTAL (3 * STG)          // 61440

#define CAND_EPS 1e-2f
#define MAXCAND 32

// ---------------- device scratch (static, no allocs) ----------------
__device__ float              g_zf[(size_t)Nv * Cv];
__device__ float              g_cn[Nv];
__device__ float              g_emb[(size_t)Ev * Cv];
__device__ float              g_sk[Ev];
__device__ __align__(256) __nv_bfloat16 g_abig[(size_t)Nv * KBIG];
__device__ __align__(256) __nv_bfloat16 g_bbig[(size_t)Ev * KBIG];
__device__ float              g_t[(size_t)Nv * Ev];   // 1 GiB
__device__ unsigned long long g_rowmax[Nv];
__device__ float              g_rowm[Nv];
__device__ float              g_rowr[Nv];
__device__ int                g_idx[Nv];
__device__ float              g_avgp[Ev];
__device__ int                g_q[Bv];
__device__ float              g_acc[8];

__device__ __forceinline__ unsigned int ford(float f) {
    unsigned int u = __float_as_uint(f);
    return (u & 0x80000000u) ? ~u : (u | 0x80000000u);
}

// ---------------- PTX helpers (base-target only) ----------------
__device__ __forceinline__ uint32_t smem_u32(const void* p) {
    uint32_t a;
    asm("{ .reg .u64 t; cvta.to.shared.u64 t, %1; cvt.u32.u64 %0, t; }" : "=r"(a) : "l"(p));
    return a;
}
__device__ __forceinline__ void cp16(uint32_t dst, const void* src) {
    asm volatile("cp.async.cg.shared.global [%0], [%1], 16;" :: "r"(dst), "l"(src) : "memory");
}
__device__ __forceinline__ void cp_commit() {
    asm volatile("cp.async.commit_group;" ::: "memory");
}
template <int N>
__device__ __forceinline__ void cp_wait() {
    asm volatile("cp.async.wait_group %0;" :: "n"(N) : "memory");
}
__device__ __forceinline__ void ldmx4(uint32_t& r0, uint32_t& r1, uint32_t& r2, uint32_t& r3,
                                      uint32_t addr) {
    asm volatile("ldmatrix.sync.aligned.m8n8.x4.shared.b16 {%0,%1,%2,%3}, [%4];"
                 : "=r"(r0), "=r"(r1), "=r"(r2), "=r"(r3) : "r"(addr));
}
__device__ __forceinline__ void hmma(float& c0, float& c1, float& c2, float& c3,
                                     uint32_t a0, uint32_t a1, uint32_t a2, uint32_t a3,
                                     uint32_t b0, uint32_t b1) {
    asm volatile(
        "mma.sync.aligned.m16n8k16.row.col.f32.bf16.bf16.f32 "
        "{%0,%1,%2,%3}, {%4,%5,%6,%7}, {%8,%9}, {%0,%1,%2,%3};"
        : "+f"(c0), "+f"(c1), "+f"(c2), "+f"(c3)
        : "r"(a0), "r"(a1), "r"(a2), "r"(a3), "r"(b0), "r"(b1));
}

// ---------------- init ----------------
__global__ void k_init(const void* qraw) {
    int i = blockIdx.x * blockDim.x + threadIdx.x;
    if (i < Ev) g_avgp[i] = 0.0f;
    if (i < Nv) g_rowmax[i] = 0ull;
    if (i == 0) {
        const unsigned int* w32 = (const unsigned int*)qraw;
        bool is64 = true;
        for (int b = 0; b < 8; b++) if (w32[2 * b + 1] != 0u) is64 = false;
        int s = 0;
        for (int b = 0; b < Bv; b++) {
            int q = is64 ? (int)w32[2 * b] : (int)((const int*)qraw)[b];
            g_q[b] = q;
            s += q + 1;
        }
        for (int j = 0; j < 8; j++) g_acc[j] = 0.0f;
        g_acc[1] = (float)s;
    }
}

// ---------------- normalize z + emit bf16 split ----------------
__global__ __launch_bounds__(256) void k_norm_z(const float* __restrict__ z) {
    __shared__ float sm[Cv][Wv + 1];
    __shared__ float sinv[Wv];
    int bh = blockIdx.x;
    int tid = threadIdx.x;
    const float* zp = z + (size_t)(bh >> 5) * Cv * (Hv * Wv) + (size_t)(bh & 31) * Wv;
    for (int it = 0; it < 32; ++it) {
        int l = it * 256 + tid;
        int c = l >> 5, w = l & 31;
        sm[c][w] = zp[(size_t)c * (Hv * Wv) + w];
    }
    __syncthreads();
    int w = tid >> 3, part = tid & 7;
    float s = 0.0f;
    for (int c = part; c < Cv; c += 8) { float v = sm[c][w]; s += v * v; }
    s += __shfl_xor_sync(~0u, s, 1);
    s += __shfl_xor_sync(~0u, s, 2);
    s += __shfl_xor_sync(~0u, s, 4);
    if (part == 0) {
        float inv = 1.0f / fmaxf(sqrtf(s), 1e-12f);
        sinv[w] = inv;
        g_cn[bh * 32 + w] = s * inv * inv;
    }
    __syncthreads();
    for (int w2 = 0; w2 < 32; ++w2) {
        int n = bh * 32 + w2;
        float v = sm[tid][w2] * sinv[w2];
        g_zf[(size_t)n * Cv + tid] = v;
        __nv_bfloat16 h = __float2bfloat16(v);
        __nv_bfloat16 l = __float2bfloat16(v - __bfloat162float(h));
        size_t base = (size_t)n * KBIG;
        g_abig[base + tid]       = h;
        g_abig[base + 256 + tid] = l;
        g_abig[base + 512 + tid] = h;
    }
}

// ---------------- normalize embedding + emit bf16 split ----------------
__global__ __launch_bounds__(256) void k_norm_emb(const float* __restrict__ e) {
    int k = blockIdx.x, tid = threadIdx.x;
    float v = e[(size_t)k * Cv + tid];
    float s = v * v;
    for (int o = 16; o; o >>= 1) s += __shfl_xor_sync(~0u, s, o);
    __shared__ float ws[8];
    if ((tid & 31) == 0) ws[tid >> 5] = s;
    __syncthreads();
    if (tid < 8) {
        float t = ws[tid];
        for (int o = 4; o; o >>= 1) t += __shfl_xor_sync(0xffu, t, o);
        if (tid == 0) ws[0] = t;
    }
    __syncthreads();
    float tot = ws[0];
    float inv = 1.0f / fmaxf(sqrtf(tot), 1e-12f);
    float vn = v * inv;
    g_emb[(size_t)k * Cv + tid] = vn;
    if (tid == 0) g_sk[k] = tot * inv * inv;
    __nv_bfloat16 h = __float2bfloat16(vn);
    __nv_bfloat16 l = __float2bfloat16(vn - __bfloat162float(h));
    size_t base = (size_t)k * KBIG;
    g_bbig[base + tid]       = h;
    g_bbig[base + 256 + tid] = h;
    g_bbig[base + 512 + tid] = l;
}

// ---------------- HMMA GEMM (ldmatrix): t = 200*G - 100*s_k, fused row argmax ----------------
__device__ __forceinline__ void load_stage(uint32_t sbase, int s, const char* Ab,
                                           const char* Bb, int kt, int tid) {
    uint32_t base = sbase + s * STG;
    const char* Asrc = Ab + kt * (BK * 2);
#pragma unroll
    for (int i = 0; i < 2; i++) {
        int u = tid + i * 256;
        int r = u >> 2, c = u & 3;
        cp16(base + r * ROWB + c * 16, Asrc + (size_t)r * (KBIG * 2) + c * 16);
    }
    uint32_t bbase = base + BM * ROWB;
    const char* Bsrc = Bb + kt * (BK * 2);
#pragma unroll
    for (int i = 0; i < 2; i++) {
        int u = tid + i * 256;
        int r = u >> 2, c = u & 3;
        cp16(bbase + r * ROWB + c * 16, Bsrc + (size_t)r * (KBIG * 2) + c * 16);
    }
}

__global__ void __launch_bounds__(256) k_mma() {
    extern __shared__ char smem[];
    uint32_t sbase = smem_u32(smem);
    int tid = threadIdx.x, wid = tid >> 5, lane = tid & 31;
    int g = lane >> 2, tig = lane & 3;
    int warpM = wid >> 2, warpN = wid & 3;          // 2 x 4
    int bm = blockIdx.y * BM, bn = blockIdx.x * BN;

    const char* Ab = (const char*)g_abig + (size_t)bm * (KBIG * 2);
    const char* Bb = (const char*)g_bbig + (size_t)bn * (KBIG * 2);

    // ldmatrix per-lane offsets
    int aoff = ((((lane >> 3) & 1) * 8 + (lane & 7)) * ROWB) + ((lane >> 4) * 16);
    int boff = ((((lane >> 4) & 1) * 8 + (lane & 7)) * ROWB) + (((lane >> 3) & 1) * 16);
    uint32_t abase = sbase + (warpM * 64) * ROWB + aoff;
    uint32_t bbase = sbase + BM * ROWB + (warpN * 32) * ROWB + boff;

    float acc[4][4][4];
#pragma unroll
    for (int mi = 0; mi < 4; mi++)
#pragma unroll
        for (int ni = 0; ni < 4; ni++)
#pragma unroll
            for (int r = 0; r < 4; r++) acc[mi][ni][r] = 0.0f;

    load_stage(sbase, 0, Ab, Bb, 0, tid); cp_commit();
    load_stage(sbase, 1, Ab, Bb, 1, tid); cp_commit();

    for (int kt = 0; kt < NKT; kt++) {
        cp_wait<1>();
        __syncthreads();
        if (kt + 2 < NKT) load_stage(sbase, (kt + 2) % 3, Ab, Bb, kt + 2, tid);
        cp_commit();

        uint32_t stg = (uint32_t)((kt % 3) * STG);
#pragma unroll
        for (int k16 = 0; k16 < 2; k16++) {
            uint32_t koff = k16 * 32;
            uint32_t Ar[4][4], Br[4][2];
#pragma unroll
            for (int mi = 0; mi < 4; mi++)
                ldmx4(Ar[mi][0], Ar[mi][1], Ar[mi][2], Ar[mi][3],
                      abase + stg + mi * 16 * ROWB + koff);
#pragma unroll
            for (int nip = 0; nip < 2; nip++)
                ldmx4(Br[2 * nip][0], Br[2 * nip][1], Br[2 * nip + 1][0], Br[2 * nip + 1][1],
                      bbase + stg + nip * 16 * ROWB + koff);
#pragma unroll
            for (int mi = 0; mi < 4; mi++)
#pragma unroll
                for (int ni = 0; ni < 4; ni++)
                    hmma(acc[mi][ni][0], acc[mi][ni][1], acc[mi][ni][2], acc[mi][ni][3],
                         Ar[mi][0], Ar[mi][1], Ar[mi][2], Ar[mi][3],
                         Br[ni][0], Br[ni][1]);
        }
        __syncthreads();
    }

    // epilogue
    int rowb = bm + warpM * 64;
    int colb = bn + warpN * 32;
    float skv[4][2];
#pragma unroll
    for (int ni = 0; ni < 4; ni++) {
        int c0 = colb + ni * 8 + 2 * tig;
        skv[ni][0] = __ldg(&g_sk[c0]);
        skv[ni][1] = __ldg(&g_sk[c0 + 1]);
    }
    float rv[4][2]; int rc[4][2];
#pragma unroll
    for (int mi = 0; mi < 4; mi++) { rv[mi][0] = rv[mi][1] = -3.4e38f; rc[mi][0] = rc[mi][1] = 0x7fffffff; }

#pragma unroll
    for (int mi = 0; mi < 4; mi++) {
        int r0 = rowb + mi * 16 + g;
        float* p0 = g_t + (size_t)r0 * Ev;
        float* p1 = g_t + (size_t)(r0 + 8) * Ev;
#pragma unroll
        for (int ni = 0; ni < 4; ni++) {
            int c0 = colb + ni * 8 + 2 * tig;
            float t00 = 200.0f * acc[mi][ni][0] - 100.0f * skv[ni][0];
            float t01 = 200.0f * acc[mi][ni][1] - 100.0f * skv[ni][1];
            float t10 = 200.0f * acc[mi][ni][2] - 100.0f * skv[ni][0];
            float t11 = 200.0f * acc[mi][ni][3] - 100.0f * skv[ni][1];
            *(float2*)(p0 + c0) = make_float2(t00, t01);
            *(float2*)(p1 + c0) = make_float2(t10, t11);
            if (t00 > rv[mi][0]) { rv[mi][0] = t00; rc[mi][0] = c0; }
            if (t01 > rv[mi][0]) { rv[mi][0] = t01; rc[mi][0] = c0 + 1; }
            if (t10 > rv[mi][1]) { rv[mi][1] = t10; rc[mi][1] = c0; }
            if (t11 > rv[mi][1]) { rv[mi][1] = t11; rc[mi][1] = c0 + 1; }
        }
    }
#pragma unroll
    for (int mi = 0; mi < 4; mi++)
#pragma unroll
        for (int h = 0; h < 2; h++) {
#pragma unroll
            for (int o = 1; o < 4; o <<= 1) {
                float ov = __shfl_xor_sync(~0u, rv[mi][h], o);
                int   oc = __shfl_xor_sync(~0u, rc[mi][h], o);
                if (ov > rv[mi][h] || (ov == rv[mi][h] && oc < rc[mi][h])) {
                    rv[mi][h] = ov; rc[mi][h] = oc;
                }
            }
            if (tig == 0) {
                int row = rowb + mi * 16 + g + h * 8;
                unsigned long long key =
                    ((unsigned long long)ford(rv[mi][h]) << 32) |
                    (unsigned long long)(0xFFFFFFFFu - (unsigned)rc[mi][h]);
                atomicMax(&g_rowmax[row], key);
            }
        }
}

// ---------------- row pass: Z, U, candidates + exact argmin refine ----------------
__global__ __launch_bounds__(256) void k_rowstats() {
    int n = blockIdx.x, tid = threadIdx.x;
    unsigned long long key = g_rowmax[n];
    unsigned int o = (unsigned int)(key >> 32);
    unsigned int ub = (o & 0x80000000u) ? (o & 0x7FFFFFFFu) : ~o;
    float m = __uint_as_float(ub);
    int kidx = (int)(0xFFFFFFFFu - (unsigned int)(key & 0xFFFFFFFFull));

    __shared__ int s_cand[MAXCAND];
    __shared__ int s_cnt;
    __shared__ int s_bidx;
    __shared__ float s_bt;
    if (tid == 0) { s_cnt = 0; s_bidx = kidx; s_bt = m; }
    __syncthreads();

    float thr = m - CAND_EPS;
    const float4* row = (const float4*)(g_t + (size_t)n * Ev);
    float Z = 0.0f, U = 0.0f;
    for (int i = tid; i < Ev / 4; i += 256) {
        float4 v = row[i];
        float u0 = v.x - m, u1 = v.y - m, u2 = v.z - m, u3 = v.w - m;
        float e0 = __expf(u0), e1 = __expf(u1), e2 = __expf(u2), e3 = __expf(u3);
        Z += e0 + e1 + e2 + e3;
        U += e0 * u0 + e1 * u1 + e2 * u2 + e3 * u3;
        if (v.x > thr) { int p = atomicAdd(&s_cnt, 1); if (p < MAXCAND) s_cand[p] = 4 * i; }
        if (v.y > thr) { int p = atomicAdd(&s_cnt, 1); if (p < MAXCAND) s_cand[p] = 4 * i + 1; }
        if (v.z > thr) { int p = atomicAdd(&s_cnt, 1); if (p < MAXCAND) s_cand[p] = 4 * i + 2; }
        if (v.w > thr) { int p = atomicAdd(&s_cnt, 1); if (p < MAXCAND) s_cand[p] = 4 * i + 3; }
    }
    for (int off = 16; off; off >>= 1) {
        Z += __shfl_xor_sync(~0u, Z, off);
        U += __shfl_xor_sync(~0u, U, off);
    }
    __shared__ float wz[8], wu[8];
    if ((tid & 31) == 0) { wz[tid >> 5] = Z; wu[tid >> 5] = U; }
    __syncthreads();

    int nc = min(s_cnt, MAXCAND);
    if (nc >= 2 && tid < 32) {
        float bt = -3.4e38f; int bc = 0x7fffffff;
        if (tid < nc) {
            int k = s_cand[tid];
            const float* ap = g_zf + (size_t)n * Cv;
            const float* bp = g_emb + (size_t)k * Cv;
            float dot = 0.0f;
#pragma unroll 8
            for (int c = 0; c < Cv; c++) dot = fmaf(__ldg(ap + c), __ldg(bp + c), dot);
            bt = 200.0f * dot - 100.0f * __ldg(&g_sk[k]);
            bc = k;
        }
#pragma unroll
        for (int off2 = 1; off2 < 32; off2 <<= 1) {
            float ov = __shfl_xor_sync(~0u, bt, off2);
            int   oc = __shfl_xor_sync(~0u, bc, off2);
            if (ov > bt || (ov == bt && oc < bc)) { bt = ov; bc = oc; }
        }
        if (tid == 0) { s_bidx = bc; s_bt = bt; }
    }
    __syncthreads();

    if (tid == 0) {
        float Zt = 0.0f, Ut = 0.0f;
        for (int w = 0; w < 8; w++) { Zt += wz[w]; Ut += wu[w]; }
        g_rowm[n] = m;
        g_rowr[n] = 1.0f / Zt;
        g_idx[n] = s_bidx;
        atomicAdd(&g_acc[2], __logf(Zt) - Ut / Zt);
        float dmin = g_cn[n] - 0.01f * s_bt;
        int b = n >> 10, w = n & 31;
        if (w <= g_q[b]) atomicAdd(&g_acc[0], dmin);
    }
}

// ---------------- column pass ----------------
__global__ __launch_bounds__(256) void k_colsum() {
    __shared__ float sm_m[512], sm_r[512];
    int col = blockIdx.x * 256 + threadIdx.x;
    int n0 = blockIdx.y * 512;
    for (int i = threadIdx.x; i < 512; i += 256) {
        sm_m[i] = g_rowm[n0 + i];
        sm_r[i] = g_rowr[n0 + i];
    }
    __syncthreads();
    float acc = 0.0f;
#pragma unroll 8
    for (int i = 0; i < 512; i++) {
        float t = g_t[(size_t)(n0 + i) * Ev + col];
        acc += __expf(t - sm_m[i]) * sm_r[i];
    }
    atomicAdd(&g_avgp[col], acc);
}

// ---------------- avg entropy ----------------
__global__ __launch_bounds__(256) void k_avgent() {
    int k = blockIdx.x * 256 + threadIdx.x;
    float ap = g_avgp[k] * (1.0f / (float)Nv);
    float v = -ap * __logf(ap + 1e-5f);
    for (int o = 16; o; o >>= 1) v += __shfl_xor_sync(~0u, v, o);
    __shared__ float ws[8];
    if ((threadIdx.x & 31) == 0) ws[threadIdx.x >> 5] = v;
    __syncthreads();
    if (threadIdx.x == 0) {
        float t = 0.0f;
        for (int w = 0; w < 8; w++) t += ws[w];
        atomicAdd(&g_acc[3], t);
    }
}

// ---------------- dead code rate ----------------
__global__ void k_dead() {
    int j = threadIdx.x;
    int v = g_idx[j];
    int same = 1;
    for (int b = 1; b < Bv; b++) same &= (g_idx[b * 1024 + j] == v);
    for (int o = 16; o; o >>= 1) same += __shfl_xor_sync(~0u, same, o);
    __shared__ int ws[32];
    if ((j & 31) == 0) ws[j >> 5] = same;
    __syncthreads();
    if (j < 32) {
        int t = ws[j];
        for (int o = 16; o; o >>= 1) t += __shfl_xor_sync(~0u, t, o);
        if (j == 0) g_acc[4] = (float)t;
    }
}

// ---------------- z_q output ----------------
__global__ __launch_bounds__(256) void k_output(float* __restrict__ out) {
    __shared__ float sm[Cv][Wv + 1];
    int bh = blockIdx.x, tid = threadIdx.x;
    for (int w = 0; w < 32; ++w) {
        int n = bh * 32 + w;
        int k = g_idx[n];
        float zf = g_zf[(size_t)n * Cv + tid];
        float e  = g_emb[(size_t)k * Cv + tid];
        sm[tid][w] = zf + (e - zf);
    }
    __syncthreads();
    float* op = out + (size_t)(bh >> 5) * Cv * (Hv * Wv) + (size_t)(bh & 31) * Wv;
    for (int it = 0; it < 32; ++it) {
        int l = it * 256 + tid;
        int c = l >> 5, w = l & 31;
        op[(size_t)c * (Hv * Wv) + w] = sm[c][w];
    }
}

// ---------------- scalars + idx ----------------
__global__ void k_finalize(float* __restrict__ out, int out_size) {
    int i = blockIdx.x * blockDim.x + threadIdx.x;
    if (i < Nv && (S0 + 4 + i) < out_size) out[S0 + 4 + i] = (float)g_idx[i];
    if (i == 0 && (S0 + 3) < out_size) {
        float denom = g_acc[1];
        float vq = g_acc[0] / (256.0f * denom);
        out[S0 + 0] = vq;
        out[S0 + 1] = 0.25f * vq;
        float sample = g_acc[2] * (1.0f / (float)Nv);
        out[S0 + 2] = 0.1f * (sample - g_acc[3]);
        out[S0 + 3] = g_acc[4] * (1.0f / 1024.0f);
    }
}

extern "C" void kernel_launch(void* const* d_in, const int* in_sizes, int n_in,
                              void* d_out, int out_size) {
    const float* z   = (const float*)d_in[0];
    const float* emb = (const float*)d_in[1];
    const void*  q   = d_in[2];
    float* out = (float*)d_out;

    cudaFuncSetAttribute(k_mma, cudaFuncAttributeMaxDynamicSharedMemorySize, SM_TOTAL);

    k_init<<<64, 256>>>(q);
    k_norm_z<<<Bv * Hv, 256>>>(z);
    k_norm_emb<<<Ev, 256>>>(emb);
    dim3 gg(Ev / BN, Nv / BM);    // 128 x 128 tiles
    k_mma<<<gg, 256, SM_TOTAL>>>();
    k_rowstats<<<Nv, 256>>>();
    dim3 gc(Ev / 256, Nv / 512);
    k_colsum<<<gc, 256>>>();
    k_avgent<<<Ev / 256, 256>>>();
    k_dead<<<1, 1024>>>();
    k_output<<<Bv * Hv, 256>>>(out);
    k_finalize<<<64, 256>>>(out, out_size);
}

// round 13
// speedup vs baseline: 1.6348x; 1.1955x over previous
#include <cuda_runtime.h>
#include <cuda_bf16.h>
#include <cuda_fp16.h>
#include <math.h>
#include <stdint.h>

// Problem dims (fixed)
#define Bv   16
#define Cv   256
#define Hv   32
#define Wv   32
#define Nv   16384          // B*H*W tokens
#define Ev   16384          // n_e codes
#define S0   4194304        // B*C*H*W = start of scalar outputs

// GEMM tiling — fp16 2-term split: A=[hi|lo], B=[hi|hi]
#define KBIG 512
#define BM   128
#define BN   128
#define BK   32
#define NKT  (KBIG / BK)    // 16 k-iterations
#define ROWB 80             // padded smem row stride in bytes
#define STG  (2 * BM * ROWB)        // 20480 bytes per stage (A + B)
#define SM_TOTAL (3 * STG)          // 61440

#define CAND_EPS 5e-2f
#define MAXCAND 32

// ---------------- device scratch (static, no allocs) ----------------
__device__ float              g_zf[(size_t)Nv * Cv];
__device__ float              g_cn[Nv];
__device__ float              g_emb[(size_t)Ev * Cv];
__device__ float              g_sk[Ev];
__device__ __align__(256) __half g_abig[(size_t)Nv * KBIG];
__device__ __align__(256) __half g_bbig[(size_t)Ev * KBIG];
__device__ float              g_t[(size_t)Nv * Ev];   // 1 GiB
__device__ unsigned long long g_rowmax[Nv];
__device__ float              g_rowm[Nv];
__device__ float              g_rowr[Nv];
__device__ int                g_idx[Nv];
__device__ float              g_avgp[Ev];
__device__ int                g_q[Bv];
__device__ float              g_acc[8];

__device__ __forceinline__ unsigned int ford(float f) {
    unsigned int u = __float_as_uint(f);
    return (u & 0x80000000u) ? ~u : (u | 0x80000000u);
}

// ---------------- PTX helpers (base-target only) ----------------
__device__ __forceinline__ uint32_t smem_u32(const void* p) {
    uint32_t a;
    asm("{ .reg .u64 t; cvta.to.shared.u64 t, %1; cvt.u32.u64 %0, t; }" : "=r"(a) : "l"(p));
    return a;
}
__device__ __forceinline__ void cp16(uint32_t dst, const void* src) {
    asm volatile("cp.async.cg.shared.global [%0], [%1], 16;" :: "r"(dst), "l"(src) : "memory");
}
__device__ __forceinline__ void cp_commit() {
    asm volatile("cp.async.commit_group;" ::: "memory");
}
template <int N>
__device__ __forceinline__ void cp_wait() {
    asm volatile("cp.async.wait_group %0;" :: "n"(N) : "memory");
}
__device__ __forceinline__ void ldmx4(uint32_t& r0, uint32_t& r1, uint32_t& r2, uint32_t& r3,
                                      uint32_t addr) {
    asm volatile("ldmatrix.sync.aligned.m8n8.x4.shared.b16 {%0,%1,%2,%3}, [%4];"
                 : "=r"(r0), "=r"(r1), "=r"(r2), "=r"(r3) : "r"(addr));
}
__device__ __forceinline__ void hmma(float& c0, float& c1, float& c2, float& c3,
                                     uint32_t a0, uint32_t a1, uint32_t a2, uint32_t a3,
                                     uint32_t b0, uint32_t b1) {
    asm volatile(
        "mma.sync.aligned.m16n8k16.row.col.f32.f16.f16.f32 "
        "{%0,%1,%2,%3}, {%4,%5,%6,%7}, {%8,%9}, {%0,%1,%2,%3};"
        : "+f"(c0), "+f"(c1), "+f"(c2), "+f"(c3)
        : "r"(a0), "r"(a1), "r"(a2), "r"(a3), "r"(b0), "r"(b1));
}

// ---------------- init ----------------
__global__ void k_init(const void* qraw) {
    int i = blockIdx.x * blockDim.x + threadIdx.x;
    if (i < Ev) g_avgp[i] = 0.0f;
    if (i < Nv) g_rowmax[i] = 0ull;
    if (i == 0) {
        const unsigned int* w32 = (const unsigned int*)qraw;
        bool is64 = true;
        for (int b = 0; b < 8; b++) if (w32[2 * b + 1] != 0u) is64 = false;
        int s = 0;
        for (int b = 0; b < Bv; b++) {
            int q = is64 ? (int)w32[2 * b] : (int)((const int*)qraw)[b];
            g_q[b] = q;
            s += q + 1;
        }
        for (int j = 0; j < 8; j++) g_acc[j] = 0.0f;
        g_acc[1] = (float)s;
    }
}

// ---------------- normalize z + emit fp16 split ----------------
__global__ __launch_bounds__(256) void k_norm_z(const float* __restrict__ z) {
    __shared__ float sm[Cv][Wv + 1];
    __shared__ float sinv[Wv];
    int bh = blockIdx.x;
    int tid = threadIdx.x;
    const float* zp = z + (size_t)(bh >> 5) * Cv * (Hv * Wv) + (size_t)(bh & 31) * Wv;
    for (int it = 0; it < 32; ++it) {
        int l = it * 256 + tid;
        int c = l >> 5, w = l & 31;
        sm[c][w] = zp[(size_t)c * (Hv * Wv) + w];
    }
    __syncthreads();
    int w = tid >> 3, part = tid & 7;
    float s = 0.0f;
    for (int c = part; c < Cv; c += 8) { float v = sm[c][w]; s += v * v; }
    s += __shfl_xor_sync(~0u, s, 1);
    s += __shfl_xor_sync(~0u, s, 2);
    s += __shfl_xor_sync(~0u, s, 4);
    if (part == 0) {
        float inv = 1.0f / fmaxf(sqrtf(s), 1e-12f);
        sinv[w] = inv;
        g_cn[bh * 32 + w] = s * inv * inv;
    }
    __syncthreads();
    for (int w2 = 0; w2 < 32; ++w2) {
        int n = bh * 32 + w2;
        float v = sm[tid][w2] * sinv[w2];
        g_zf[(size_t)n * Cv + tid] = v;
        __half h = __float2half(v);
        __half l = __float2half(v - __half2float(h));
        size_t base = (size_t)n * KBIG;
        g_abig[base + tid]       = h;
        g_abig[base + 256 + tid] = l;
    }
}

// ---------------- normalize embedding + emit fp16 split ----------------
__global__ __launch_bounds__(256) void k_norm_emb(const float* __restrict__ e) {
    int k = blockIdx.x, tid = threadIdx.x;
    float v = e[(size_t)k * Cv + tid];
    float s = v * v;
    for (int o = 16; o; o >>= 1) s += __shfl_xor_sync(~0u, s, o);
    __shared__ float ws[8];
    if ((tid & 31) == 0) ws[tid >> 5] = s;
    __syncthreads();
    if (tid < 8) {
        float t = ws[tid];
        for (int o = 4; o; o >>= 1) t += __shfl_xor_sync(0xffu, t, o);
        if (tid == 0) ws[0] = t;
    }
    __syncthreads();
    float tot = ws[0];
    float inv = 1.0f / fmaxf(sqrtf(tot), 1e-12f);
    float vn = v * inv;
    g_emb[(size_t)k * Cv + tid] = vn;
    if (tid == 0) g_sk[k] = tot * inv * inv;
    __half h = __float2half(vn);
    size_t base = (size_t)k * KBIG;
    g_bbig[base + tid]       = h;
    g_bbig[base + 256 + tid] = h;
}

// ---------------- HMMA GEMM (ldmatrix): t = 200*G - 100*s_k, fused row argmax ----------------
__device__ __forceinline__ void load_stage(uint32_t sbase, int s, const char* Ab,
                                           const char* Bb, int kt, int tid) {
    uint32_t base = sbase + s * STG;
    const char* Asrc = Ab + kt * (BK * 2);
#pragma unroll
    for (int i = 0; i < 2; i++) {
        int u = tid + i * 256;
        int r = u >> 2, c = u & 3;
        cp16(base + r * ROWB + c * 16, Asrc + (size_t)r * (KBIG * 2) + c * 16);
    }
    uint32_t bbase = base + BM * ROWB;
    const char* Bsrc = Bb + kt * (BK * 2);
#pragma unroll
    for (int i = 0; i < 2; i++) {
        int u = tid + i * 256;
        int r = u >> 2, c = u & 3;
        cp16(bbase + r * ROWB + c * 16, Bsrc + (size_t)r * (KBIG * 2) + c * 16);
    }
}

__global__ void __launch_bounds__(256) k_mma() {
    extern __shared__ char smem[];
    uint32_t sbase = smem_u32(smem);
    int tid = threadIdx.x, wid = tid >> 5, lane = tid & 31;
    int g = lane >> 2, tig = lane & 3;
    int warpM = wid >> 2, warpN = wid & 3;          // 2 x 4
    int bm = blockIdx.y * BM, bn = blockIdx.x * BN;

    const char* Ab = (const char*)g_abig + (size_t)bm * (KBIG * 2);
    const char* Bb = (const char*)g_bbig + (size_t)bn * (KBIG * 2);

    // ldmatrix per-lane offsets
    int aoff = ((((lane >> 3) & 1) * 8 + (lane & 7)) * ROWB) + ((lane >> 4) * 16);
    int boff = ((((lane >> 4) & 1) * 8 + (lane & 7)) * ROWB) + (((lane >> 3) & 1) * 16);
    uint32_t abase = sbase + (warpM * 64) * ROWB + aoff;
    uint32_t bbase = sbase + BM * ROWB + (warpN * 32) * ROWB + boff;

    float acc[4][4][4];
#pragma unroll
    for (int mi = 0; mi < 4; mi++)
#pragma unroll
        for (int ni = 0; ni < 4; ni++)
#pragma unroll
            for (int r = 0; r < 4; r++) acc[mi][ni][r] = 0.0f;

    load_stage(sbase, 0, Ab, Bb, 0, tid); cp_commit();
    load_stage(sbase, 1, Ab, Bb, 1, tid); cp_commit();

    for (int kt = 0; kt < NKT; kt++) {
        cp_wait<1>();
        __syncthreads();
        if (kt + 2 < NKT) load_stage(sbase, (kt + 2) % 3, Ab, Bb, kt + 2, tid);
        cp_commit();

        uint32_t stg = (uint32_t)((kt % 3) * STG);
#pragma unroll
        for (int k16 = 0; k16 < 2; k16++) {
            uint32_t koff = k16 * 32;
            uint32_t Ar[4][4], Br[4][2];
#pragma unroll
            for (int mi = 0; mi < 4; mi++)
                ldmx4(Ar[mi][0], Ar[mi][1], Ar[mi][2], Ar[mi][3],
                      abase + stg + mi * 16 * ROWB + koff);
#pragma unroll
            for (int nip = 0; nip < 2; nip++)
                ldmx4(Br[2 * nip][0], Br[2 * nip][1], Br[2 * nip + 1][0], Br[2 * nip + 1][1],
                      bbase + stg + nip * 16 * ROWB + koff);
#pragma unroll
            for (int mi = 0; mi < 4; mi++)
#pragma unroll
                for (int ni = 0; ni < 4; ni++)
                    hmma(acc[mi][ni][0], acc[mi][ni][1], acc[mi][ni][2], acc[mi][ni][3],
                         Ar[mi][0], Ar[mi][1], Ar[mi][2], Ar[mi][3],
                         Br[ni][0], Br[ni][1]);
        }
        __syncthreads();
    }

    // epilogue
    int rowb = bm + warpM * 64;
    int colb = bn + warpN * 32;
    float skv[4][2];
#pragma unroll
    for (int ni = 0; ni < 4; ni++) {
        int c0 = colb + ni * 8 + 2 * tig;
        skv[ni][0] = __ldg(&g_sk[c0]);
        skv[ni][1] = __ldg(&g_sk[c0 + 1]);
    }
    float rv[4][2]; int rc[4][2];
#pragma unroll
    for (int mi = 0; mi < 4; mi++) { rv[mi][0] = rv[mi][1] = -3.4e38f; rc[mi][0] = rc[mi][1] = 0x7fffffff; }

#pragma unroll
    for (int mi = 0; mi < 4; mi++) {
        int r0 = rowb + mi * 16 + g;
        float* p0 = g_t + (size_t)r0 * Ev;
        float* p1 = g_t + (size_t)(r0 + 8) * Ev;
#pragma unroll
        for (int ni = 0; ni < 4; ni++) {
            int c0 = colb + ni * 8 + 2 * tig;
            float t00 = 200.0f * acc[mi][ni][0] - 100.0f * skv[ni][0];
            float t01 = 200.0f * acc[mi][ni][1] - 100.0f * skv[ni][1];
            float t10 = 200.0f * acc[mi][ni][2] - 100.0f * skv[ni][0];
            float t11 = 200.0f * acc[mi][ni][3] - 100.0f * skv[ni][1];
            *(float2*)(p0 + c0) = make_float2(t00, t01);
            *(float2*)(p1 + c0) = make_float2(t10, t11);
            if (t00 > rv[mi][0]) { rv[mi][0] = t00; rc[mi][0] = c0; }
            if (t01 > rv[mi][0]) { rv[mi][0] = t01; rc[mi][0] = c0 + 1; }
            if (t10 > rv[mi][1]) { rv[mi][1] = t10; rc[mi][1] = c0; }
            if (t11 > rv[mi][1]) { rv[mi][1] = t11; rc[mi][1] = c0 + 1; }
        }
    }
#pragma unroll
    for (int mi = 0; mi < 4; mi++)
#pragma unroll
        for (int h = 0; h < 2; h++) {
#pragma unroll
            for (int o = 1; o < 4; o <<= 1) {
                float ov = __shfl_xor_sync(~0u, rv[mi][h], o);
                int   oc = __shfl_xor_sync(~0u, rc[mi][h], o);
                if (ov > rv[mi][h] || (ov == rv[mi][h] && oc < rc[mi][h])) {
                    rv[mi][h] = ov; rc[mi][h] = oc;
                }
            }
            if (tig == 0) {
                int row = rowb + mi * 16 + g + h * 8;
                unsigned long long key =
                    ((unsigned long long)ford(rv[mi][h]) << 32) |
                    (unsigned long long)(0xFFFFFFFFu - (unsigned)rc[mi][h]);
                atomicMax(&g_rowmax[row], key);
            }
        }
}

// ---------------- row pass: Z, U, candidates + exact argmin refine (always) ----------------
__global__ __launch_bounds__(256) void k_rowstats() {
    int n = blockIdx.x, tid = threadIdx.x;
    unsigned long long key = g_rowmax[n];
    unsigned int o = (unsigned int)(key >> 32);
    unsigned int ub = (o & 0x80000000u) ? (o & 0x7FFFFFFFu) : ~o;
    float m = __uint_as_float(ub);
    int kidx = (int)(0xFFFFFFFFu - (unsigned int)(key & 0xFFFFFFFFull));

    __shared__ int s_cand[MAXCAND];
    __shared__ int s_cnt;
    __shared__ int s_bidx;
    __shared__ float s_bt;
    if (tid == 0) { s_cnt = 0; s_bidx = kidx; s_bt = m; }
    __syncthreads();

    float thr = m - CAND_EPS;
    const float4* row = (const float4*)(g_t + (size_t)n * Ev);
    float Z = 0.0f, U = 0.0f;
    for (int i = tid; i < Ev / 4; i += 256) {
        float4 v = row[i];
        float u0 = v.x - m, u1 = v.y - m, u2 = v.z - m, u3 = v.w - m;
        float e0 = __expf(u0), e1 = __expf(u1), e2 = __expf(u2), e3 = __expf(u3);
        Z += e0 + e1 + e2 + e3;
        U += e0 * u0 + e1 * u1 + e2 * u2 + e3 * u3;
        if (v.x > thr) { int p = atomicAdd(&s_cnt, 1); if (p < MAXCAND) s_cand[p] = 4 * i; }
        if (v.y > thr) { int p = atomicAdd(&s_cnt, 1); if (p < MAXCAND) s_cand[p] = 4 * i + 1; }
        if (v.z > thr) { int p = atomicAdd(&s_cnt, 1); if (p < MAXCAND) s_cand[p] = 4 * i + 2; }
        if (v.w > thr) { int p = atomicAdd(&s_cnt, 1); if (p < MAXCAND) s_cand[p] = 4 * i + 3; }
    }
    for (int off = 16; off; off >>= 1) {
        Z += __shfl_xor_sync(~0u, Z, off);
        U += __shfl_xor_sync(~0u, U, off);
    }
    __shared__ float wz[8], wu[8];
    if ((tid & 31) == 0) { wz[tid >> 5] = Z; wu[tid >> 5] = U; }
    __syncthreads();

    // exact refinement — always (winner is always a candidate since t_max > thr)
    int nc = min(s_cnt, MAXCAND);
    if (tid < 32) {
        float bt = -3.4e38f; int bc = 0x7fffffff;
        if (tid < nc) {
            int k = s_cand[tid];
            const float* ap = g_zf + (size_t)n * Cv;
            const float* bp = g_emb + (size_t)k * Cv;
            float dot = 0.0f;
#pragma unroll 8
            for (int c = 0; c < Cv; c++) dot = fmaf(__ldg(ap + c), __ldg(bp + c), dot);
            bt = 200.0f * dot - 100.0f * __ldg(&g_sk[k]);
            bc = k;
        }
#pragma unroll
        for (int off2 = 1; off2 < 32; off2 <<= 1) {
            float ov = __shfl_xor_sync(~0u, bt, off2);
            int   oc = __shfl_xor_sync(~0u, bc, off2);
            if (ov > bt || (ov == bt && oc < bc)) { bt = ov; bc = oc; }
        }
        if (tid == 0 && nc > 0) { s_bidx = bc; s_bt = bt; }
    }
    __syncthreads();

    if (tid == 0) {
        float Zt = 0.0f, Ut = 0.0f;
        for (int w = 0; w < 8; w++) { Zt += wz[w]; Ut += wu[w]; }
        g_rowm[n] = m;
        g_rowr[n] = 1.0f / Zt;
        g_idx[n] = s_bidx;
        atomicAdd(&g_acc[2], __logf(Zt) - Ut / Zt);
        float dmin = g_cn[n] - 0.01f * s_bt;
        int b = n >> 10, w = n & 31;
        if (w <= g_q[b]) atomicAdd(&g_acc[0], dmin);
    }
}

// ---------------- column pass ----------------
__global__ __launch_bounds__(256) void k_colsum() {
    __shared__ float sm_m[512], sm_r[512];
    int col = blockIdx.x * 256 + threadIdx.x;
    int n0 = blockIdx.y * 512;
    for (int i = threadIdx.x; i < 512; i += 256) {
        sm_m[i] = g_rowm[n0 + i];
        sm_r[i] = g_rowr[n0 + i];
    }
    __syncthreads();
    float acc = 0.0f;
#pragma unroll 8
    for (int i = 0; i < 512; i++) {
        float t = g_t[(size_t)(n0 + i) * Ev + col];
        acc += __expf(t - sm_m[i]) * sm_r[i];
    }
    atomicAdd(&g_avgp[col], acc);
}

// ---------------- avg entropy ----------------
__global__ __launch_bounds__(256) void k_avgent() {
    int k = blockIdx.x * 256 + threadIdx.x;
    float ap = g_avgp[k] * (1.0f / (float)Nv);
    float v = -ap * __logf(ap + 1e-5f);
    for (int o = 16; o; o >>= 1) v += __shfl_xor_sync(~0u, v, o);
    __shared__ float ws[8];
    if ((threadIdx.x & 31) == 0) ws[threadIdx.x >> 5] = v;
    __syncthreads();
    if (threadIdx.x == 0) {
        float t = 0.0f;
        for (int w = 0; w < 8; w++) t += ws[w];
        atomicAdd(&g_acc[3], t);
    }
}

// ---------------- dead code rate ----------------
__global__ void k_dead() {
    int j = threadIdx.x;
    int v = g_idx[j];
    int same = 1;
    for (int b = 1; b < Bv; b++) same &= (g_idx[b * 1024 + j] == v);
    for (int o = 16; o; o >>= 1) same += __shfl_xor_sync(~0u, same, o);
    __shared__ int ws[32];
    if ((j & 31) == 0) ws[j >> 5] = same;
    __syncthreads();
    if (j < 32) {
        int t = ws[j];
        for (int o = 16; o; o >>= 1) t += __shfl_xor_sync(~0u, t, o);
        if (j == 0) g_acc[4] = (float)t;
    }
}

// ---------------- z_q output ----------------
__global__ __launch_bounds__(256) void k_output(float* __restrict__ out) {
    __shared__ float sm[Cv][Wv + 1];
    int bh = blockIdx.x, tid = threadIdx.x;
    for (int w = 0; w < 32; ++w) {
        int n = bh * 32 + w;
        int k = g_idx[n];
        float zf = g_zf[(size_t)n * Cv + tid];
        float e  = g_emb[(size_t)k * Cv + tid];
        sm[tid][w] = zf + (e - zf);
    }
    __syncthreads();
    float* op = out + (size_t)(bh >> 5) * Cv * (Hv * Wv) + (size_t)(bh & 31) * Wv;
    for (int it = 0; it < 32; ++it) {
        int l = it * 256 + tid;
        int c = l >> 5, w = l & 31;
        op[(size_t)c * (Hv * Wv) + w] = sm[c][w];
    }
}

// ---------------- scalars + idx ----------------
__global__ void k_finalize(float* __restrict__ out, int out_size) {
    int i = blockIdx.x * blockDim.x + threadIdx.x;
    if (i < Nv && (S0 + 4 + i) < out_size) out[S0 + 4 + i] = (float)g_idx[i];
    if (i == 0 && (S0 + 3) < out_size) {
        float denom = g_acc[1];
        float vq = g_acc[0] / (256.0f * denom);
        out[S0 + 0] = vq;
        out[S0 + 1] = 0.25f * vq;
        float sample = g_acc[2] * (1.0f / (float)Nv);
        out[S0 + 2] = 0.1f * (sample - g_acc[3]);
        out[S0 + 3] = g_acc[4] * (1.0f / 1024.0f);
    }
}

extern "C" void kernel_launch(void* const* d_in, const int* in_sizes, int n_in,
                              void* d_out, int out_size) {
    const float* z   = (const float*)d_in[0];
    const float* emb = (const float*)d_in[1];
    const void*  q   = d_in[2];
    float* out = (float*)d_out;

    cudaFuncSetAttribute(k_mma, cudaFuncAttributeMaxDynamicSharedMemorySize, SM_TOTAL);

    k_init<<<64, 256>>>(q);
    k_norm_z<<<Bv * Hv, 256>>>(z);
    k_norm_emb<<<Ev, 256>>>(emb);
    dim3 gg(Ev / BN, Nv / BM);    // 128 x 128 tiles
    k_mma<<<gg, 256, SM_TOTAL>>>();
    k_rowstats<<<Nv, 256>>>();
    dim3 gc(Ev / 256, Nv / 512);
    k_colsum<<<gc, 256>>>();
    k_avgent<<<Ev / 256, 256>>>();
    k_dead<<<1, 1024>>>();
    k_output<<<Bv * Hv, 256>>>(out);
    k_finalize<<<64, 256>>>(out, out_size);
}

// round 14
// speedup vs baseline: 2.2460x; 1.3739x over previous
#include <cuda_runtime.h>
#include <cuda_bf16.h>
#include <cuda_fp16.h>
#include <math.h>
#include <stdint.h>

// Problem dims (fixed)
#define Bv   16
#define Cv   256
#define Hv   32
#define Wv   32
#define Nv   16384          // B*H*W tokens
#define Ev   16384          // n_e codes
#define S0   4194304        // B*C*H*W = start of scalar outputs

// GEMM tiling — single fp16 term (exact refine absorbs the rounding)
#define KBIG 256
#define BM   128
#define BN   128
#define BK   32
#define NKT  (KBIG / BK)    // 8 k-iterations
#define ROWB 80             // padded smem row stride in bytes
#define STG  (2 * BM * ROWB)        // 20480 bytes per stage (A + B)
#define SM_TOTAL (3 * STG)          // 61440

#define CAND_EPS 0.15f
#define MAXCAND 32

// ---------------- device scratch (static, no allocs) ----------------
__device__ float              g_zf[(size_t)Nv * Cv];
__device__ float              g_cn[Nv];
__device__ float              g_emb[(size_t)Ev * Cv];
__device__ float              g_sk[Ev];
__device__ __align__(256) __half g_abig[(size_t)Nv * KBIG];
__device__ __align__(256) __half g_bbig[(size_t)Ev * KBIG];
__device__ float              g_t[(size_t)Nv * Ev];   // 1 GiB
__device__ unsigned long long g_rowmax[Nv];
__device__ float              g_rowm[Nv];
__device__ float              g_rowr[Nv];
__device__ int                g_idx[Nv];
__device__ float              g_avgp[Ev];
__device__ int                g_q[Bv];
__device__ float              g_acc[8];

__device__ __forceinline__ unsigned int ford(float f) {
    unsigned int u = __float_as_uint(f);
    return (u & 0x80000000u) ? ~u : (u | 0x80000000u);
}

// ---------------- PTX helpers (base-target only) ----------------
__device__ __forceinline__ uint32_t smem_u32(const void* p) {
    uint32_t a;
    asm("{ .reg .u64 t; cvta.to.shared.u64 t, %1; cvt.u32.u64 %0, t; }" : "=r"(a) : "l"(p));
    return a;
}
__device__ __forceinline__ void cp16(uint32_t dst, const void* src) {
    asm volatile("cp.async.cg.shared.global [%0], [%1], 16;" :: "r"(dst), "l"(src) : "memory");
}
__device__ __forceinline__ void cp_commit() {
    asm volatile("cp.async.commit_group;" ::: "memory");
}
template <int N>
__device__ __forceinline__ void cp_wait() {
    asm volatile("cp.async.wait_group %0;" :: "n"(N) : "memory");
}
__device__ __forceinline__ void ldmx4(uint32_t& r0, uint32_t& r1, uint32_t& r2, uint32_t& r3,
                                      uint32_t addr) {
    asm volatile("ldmatrix.sync.aligned.m8n8.x4.shared.b16 {%0,%1,%2,%3}, [%4];"
                 : "=r"(r0), "=r"(r1), "=r"(r2), "=r"(r3) : "r"(addr));
}
__device__ __forceinline__ void hmma(float& c0, float& c1, float& c2, float& c3,
                                     uint32_t a0, uint32_t a1, uint32_t a2, uint32_t a3,
                                     uint32_t b0, uint32_t b1) {
    asm volatile(
        "mma.sync.aligned.m16n8k16.row.col.f32.f16.f16.f32 "
        "{%0,%1,%2,%3}, {%4,%5,%6,%7}, {%8,%9}, {%0,%1,%2,%3};"
        : "+f"(c0), "+f"(c1), "+f"(c2), "+f"(c3)
        : "r"(a0), "r"(a1), "r"(a2), "r"(a3), "r"(b0), "r"(b1));
}

// ---------------- init ----------------
__global__ void k_init(const void* qraw) {
    int i = blockIdx.x * blockDim.x + threadIdx.x;
    if (i < Ev) g_avgp[i] = 0.0f;
    if (i < Nv) g_rowmax[i] = 0ull;
    if (i == 0) {
        const unsigned int* w32 = (const unsigned int*)qraw;
        bool is64 = true;
        for (int b = 0; b < 8; b++) if (w32[2 * b + 1] != 0u) is64 = false;
        int s = 0;
        for (int b = 0; b < Bv; b++) {
            int q = is64 ? (int)w32[2 * b] : (int)((const int*)qraw)[b];
            g_q[b] = q;
            s += q + 1;
        }
        for (int j = 0; j < 8; j++) g_acc[j] = 0.0f;
        g_acc[1] = (float)s;
    }
}

// ---------------- normalize z + emit fp16 ----------------
__global__ __launch_bounds__(256) void k_norm_z(const float* __restrict__ z) {
    __shared__ float sm[Cv][Wv + 1];
    __shared__ float sinv[Wv];
    int bh = blockIdx.x;
    int tid = threadIdx.x;
    const float* zp = z + (size_t)(bh >> 5) * Cv * (Hv * Wv) + (size_t)(bh & 31) * Wv;
    for (int it = 0; it < 32; ++it) {
        int l = it * 256 + tid;
        int c = l >> 5, w = l & 31;
        sm[c][w] = zp[(size_t)c * (Hv * Wv) + w];
    }
    __syncthreads();
    int w = tid >> 3, part = tid & 7;
    float s = 0.0f;
    for (int c = part; c < Cv; c += 8) { float v = sm[c][w]; s += v * v; }
    s += __shfl_xor_sync(~0u, s, 1);
    s += __shfl_xor_sync(~0u, s, 2);
    s += __shfl_xor_sync(~0u, s, 4);
    if (part == 0) {
        float inv = 1.0f / fmaxf(sqrtf(s), 1e-12f);
        sinv[w] = inv;
        g_cn[bh * 32 + w] = s * inv * inv;
    }
    __syncthreads();
    for (int w2 = 0; w2 < 32; ++w2) {
        int n = bh * 32 + w2;
        float v = sm[tid][w2] * sinv[w2];
        g_zf[(size_t)n * Cv + tid] = v;
        g_abig[(size_t)n * KBIG + tid] = __float2half(v);
    }
}

// ---------------- normalize embedding + emit fp16 ----------------
__global__ __launch_bounds__(256) void k_norm_emb(const float* __restrict__ e) {
    int k = blockIdx.x, tid = threadIdx.x;
    float v = e[(size_t)k * Cv + tid];
    float s = v * v;
    for (int o = 16; o; o >>= 1) s += __shfl_xor_sync(~0u, s, o);
    __shared__ float ws[8];
    if ((tid & 31) == 0) ws[tid >> 5] = s;
    __syncthreads();
    if (tid < 8) {
        float t = ws[tid];
        for (int o = 4; o; o >>= 1) t += __shfl_xor_sync(0xffu, t, o);
        if (tid == 0) ws[0] = t;
    }
    __syncthreads();
    float tot = ws[0];
    float inv = 1.0f / fmaxf(sqrtf(tot), 1e-12f);
    float vn = v * inv;
    g_emb[(size_t)k * Cv + tid] = vn;
    if (tid == 0) g_sk[k] = tot * inv * inv;
    g_bbig[(size_t)k * KBIG + tid] = __float2half(vn);
}

// ---------------- HMMA GEMM (ldmatrix): t = 200*G - 100*s_k, fused row argmax ----------------
__device__ __forceinline__ void load_stage(uint32_t sbase, int s, const char* Ab,
                                           const char* Bb, int kt, int tid) {
    uint32_t base = sbase + s * STG;
    const char* Asrc = Ab + kt * (BK * 2);
#pragma unroll
    for (int i = 0; i < 2; i++) {
        int u = tid + i * 256;
        int r = u >> 2, c = u & 3;
        cp16(base + r * ROWB + c * 16, Asrc + (size_t)r * (KBIG * 2) + c * 16);
    }
    uint32_t bbase = base + BM * ROWB;
    const char* Bsrc = Bb + kt * (BK * 2);
#pragma unroll
    for (int i = 0; i < 2; i++) {
        int u = tid + i * 256;
        int r = u >> 2, c = u & 3;
        cp16(bbase + r * ROWB + c * 16, Bsrc + (size_t)r * (KBIG * 2) + c * 16);
    }
}

__global__ void __launch_bounds__(256) k_mma() {
    extern __shared__ char smem[];
    uint32_t sbase = smem_u32(smem);
    int tid = threadIdx.x, wid = tid >> 5, lane = tid & 31;
    int g = lane >> 2, tig = lane & 3;
    int warpM = wid >> 2, warpN = wid & 3;          // 2 x 4
    int bm = blockIdx.y * BM, bn = blockIdx.x * BN;

    const char* Ab = (const char*)g_abig + (size_t)bm * (KBIG * 2);
    const char* Bb = (const char*)g_bbig + (size_t)bn * (KBIG * 2);

    // ldmatrix per-lane offsets
    int aoff = ((((lane >> 3) & 1) * 8 + (lane & 7)) * ROWB) + ((lane >> 4) * 16);
    int boff = ((((lane >> 4) & 1) * 8 + (lane & 7)) * ROWB) + (((lane >> 3) & 1) * 16);
    uint32_t abase = sbase + (warpM * 64) * ROWB + aoff;
    uint32_t bbase = sbase + BM * ROWB + (warpN * 32) * ROWB + boff;

    float acc[4][4][4];
#pragma unroll
    for (int mi = 0; mi < 4; mi++)
#pragma unroll
        for (int ni = 0; ni < 4; ni++)
#pragma unroll
            for (int r = 0; r < 4; r++) acc[mi][ni][r] = 0.0f;

    load_stage(sbase, 0, Ab, Bb, 0, tid); cp_commit();
    load_stage(sbase, 1, Ab, Bb, 1, tid); cp_commit();

    for (int kt = 0; kt < NKT; kt++) {
        cp_wait<1>();
        __syncthreads();
        if (kt + 2 < NKT) load_stage(sbase, (kt + 2) % 3, Ab, Bb, kt + 2, tid);
        cp_commit();

        uint32_t stg = (uint32_t)((kt % 3) * STG);
#pragma unroll
        for (int k16 = 0; k16 < 2; k16++) {
            uint32_t koff = k16 * 32;
            uint32_t Ar[4][4], Br[4][2];
#pragma unroll
            for (int mi = 0; mi < 4; mi++)
                ldmx4(Ar[mi][0], Ar[mi][1], Ar[mi][2], Ar[mi][3],
                      abase + stg + mi * 16 * ROWB + koff);
#pragma unroll
            for (int nip = 0; nip < 2; nip++)
                ldmx4(Br[2 * nip][0], Br[2 * nip][1], Br[2 * nip + 1][0], Br[2 * nip + 1][1],
                      bbase + stg + nip * 16 * ROWB + koff);
#pragma unroll
            for (int mi = 0; mi < 4; mi++)
#pragma unroll
                for (int ni = 0; ni < 4; ni++)
                    hmma(acc[mi][ni][0], acc[mi][ni][1], acc[mi][ni][2], acc[mi][ni][3],
                         Ar[mi][0], Ar[mi][1], Ar[mi][2], Ar[mi][3],
                         Br[ni][0], Br[ni][1]);
        }
        __syncthreads();
    }

    // epilogue
    int rowb = bm + warpM * 64;
    int colb = bn + warpN * 32;
    float skv[4][2];
#pragma unroll
    for (int ni = 0; ni < 4; ni++) {
        int c0 = colb + ni * 8 + 2 * tig;
        skv[ni][0] = __ldg(&g_sk[c0]);
        skv[ni][1] = __ldg(&g_sk[c0 + 1]);
    }
    float rv[4][2]; int rc[4][2];
#pragma unroll
    for (int mi = 0; mi < 4; mi++) { rv[mi][0] = rv[mi][1] = -3.4e38f; rc[mi][0] = rc[mi][1] = 0x7fffffff; }

#pragma unroll
    for (int mi = 0; mi < 4; mi++) {
        int r0 = rowb + mi * 16 + g;
        float* p0 = g_t + (size_t)r0 * Ev;
        float* p1 = g_t + (size_t)(r0 + 8) * Ev;
#pragma unroll
        for (int ni = 0; ni < 4; ni++) {
            int c0 = colb + ni * 8 + 2 * tig;
            float t00 = 200.0f * acc[mi][ni][0] - 100.0f * skv[ni][0];
            float t01 = 200.0f * acc[mi][ni][1] - 100.0f * skv[ni][1];
            float t10 = 200.0f * acc[mi][ni][2] - 100.0f * skv[ni][0];
            float t11 = 200.0f * acc[mi][ni][3] - 100.0f * skv[ni][1];
            *(float2*)(p0 + c0) = make_float2(t00, t01);
            *(float2*)(p1 + c0) = make_float2(t10, t11);
            if (t00 > rv[mi][0]) { rv[mi][0] = t00; rc[mi][0] = c0; }
            if (t01 > rv[mi][0]) { rv[mi][0] = t01; rc[mi][0] = c0 + 1; }
            if (t10 > rv[mi][1]) { rv[mi][1] = t10; rc[mi][1] = c0; }
            if (t11 > rv[mi][1]) { rv[mi][1] = t11; rc[mi][1] = c0 + 1; }
        }
    }
#pragma unroll
    for (int mi = 0; mi < 4; mi++)
#pragma unroll
        for (int h = 0; h < 2; h++) {
#pragma unroll
            for (int o = 1; o < 4; o <<= 1) {
                float ov = __shfl_xor_sync(~0u, rv[mi][h], o);
                int   oc = __shfl_xor_sync(~0u, rc[mi][h], o);
                if (ov > rv[mi][h] || (ov == rv[mi][h] && oc < rc[mi][h])) {
                    rv[mi][h] = ov; rc[mi][h] = oc;
                }
            }
            if (tig == 0) {
                int row = rowb + mi * 16 + g + h * 8;
                unsigned long long key =
                    ((unsigned long long)ford(rv[mi][h]) << 32) |
                    (unsigned long long)(0xFFFFFFFFu - (unsigned)rc[mi][h]);
                atomicMax(&g_rowmax[row], key);
            }
        }
}

// ---------------- row pass: Z, U, candidates + exact argmin refine (always) ----------------
__global__ __launch_bounds__(256) void k_rowstats() {
    int n = blockIdx.x, tid = threadIdx.x;
    unsigned long long key = g_rowmax[n];
    unsigned int o = (unsigned int)(key >> 32);
    unsigned int ub = (o & 0x80000000u) ? (o & 0x7FFFFFFFu) : ~o;
    float m = __uint_as_float(ub);
    int kidx = (int)(0xFFFFFFFFu - (unsigned int)(key & 0xFFFFFFFFull));

    __shared__ int s_cand[MAXCAND];
    __shared__ int s_cnt;
    __shared__ int s_bidx;
    __shared__ float s_bt;
    if (tid == 0) { s_cnt = 0; s_bidx = kidx; s_bt = m; }
    __syncthreads();

    float thr = m - CAND_EPS;
    const float4* row = (const float4*)(g_t + (size_t)n * Ev);
    float Z = 0.0f, U = 0.0f;
    for (int i = tid; i < Ev / 4; i += 256) {
        float4 v = row[i];
        float u0 = v.x - m, u1 = v.y - m, u2 = v.z - m, u3 = v.w - m;
        float e0 = __expf(u0), e1 = __expf(u1), e2 = __expf(u2), e3 = __expf(u3);
        Z += e0 + e1 + e2 + e3;
        U += e0 * u0 + e1 * u1 + e2 * u2 + e3 * u3;
        if (v.x > thr) { int p = atomicAdd(&s_cnt, 1); if (p < MAXCAND) s_cand[p] = 4 * i; }
        if (v.y > thr) { int p = atomicAdd(&s_cnt, 1); if (p < MAXCAND) s_cand[p] = 4 * i + 1; }
        if (v.z > thr) { int p = atomicAdd(&s_cnt, 1); if (p < MAXCAND) s_cand[p] = 4 * i + 2; }
        if (v.w > thr) { int p = atomicAdd(&s_cnt, 1); if (p < MAXCAND) s_cand[p] = 4 * i + 3; }
    }
    for (int off = 16; off; off >>= 1) {
        Z += __shfl_xor_sync(~0u, Z, off);
        U += __shfl_xor_sync(~0u, U, off);
    }
    __shared__ float wz[8], wu[8];
    if ((tid & 31) == 0) { wz[tid >> 5] = Z; wu[tid >> 5] = U; }
    __syncthreads();

    // exact refinement — always (winner is always a candidate since t_max > thr)
    int nc = min(s_cnt, MAXCAND);
    if (tid < 32) {
        float bt = -3.4e38f; int bc = 0x7fffffff;
        if (tid < nc) {
            int k = s_cand[tid];
            const float* ap = g_zf + (size_t)n * Cv;
            const float* bp = g_emb + (size_t)k * Cv;
            float dot = 0.0f;
#pragma unroll 8
            for (int c = 0; c < Cv; c++) dot = fmaf(__ldg(ap + c), __ldg(bp + c), dot);
            bt = 200.0f * dot - 100.0f * __ldg(&g_sk[k]);
            bc = k;
        }
#pragma unroll
        for (int off2 = 1; off2 < 32; off2 <<= 1) {
            float ov = __shfl_xor_sync(~0u, bt, off2);
            int   oc = __shfl_xor_sync(~0u, bc, off2);
            if (ov > bt || (ov == bt && oc < bc)) { bt = ov; bc = oc; }
        }
        if (tid == 0 && nc > 0) { s_bidx = bc; s_bt = bt; }
    }
    __syncthreads();

    if (tid == 0) {
        float Zt = 0.0f, Ut = 0.0f;
        for (int w = 0; w < 8; w++) { Zt += wz[w]; Ut += wu[w]; }
        g_rowm[n] = m;
        g_rowr[n] = 1.0f / Zt;
        g_idx[n] = s_bidx;
        atomicAdd(&g_acc[2], __logf(Zt) - Ut / Zt);
        float dmin = g_cn[n] - 0.01f * s_bt;
        int b = n >> 10, w = n & 31;
        if (w <= g_q[b]) atomicAdd(&g_acc[0], dmin);
    }
}

// ---------------- column pass ----------------
__global__ __launch_bounds__(256) void k_colsum() {
    __shared__ float sm_m[512], sm_r[512];
    int col = blockIdx.x * 256 + threadIdx.x;
    int n0 = blockIdx.y * 512;
    for (int i = threadIdx.x; i < 512; i += 256) {
        sm_m[i] = g_rowm[n0 + i];
        sm_r[i] = g_rowr[n0 + i];
    }
    __syncthreads();
    float acc = 0.0f;
#pragma unroll 8
    for (int i = 0; i < 512; i++) {
        float t = g_t[(size_t)(n0 + i) * Ev + col];
        acc += __expf(t - sm_m[i]) * sm_r[i];
    }
    atomicAdd(&g_avgp[col], acc);
}

// ---------------- avg entropy ----------------
__global__ __launch_bounds__(256) void k_avgent() {
    int k = blockIdx.x * 256 + threadIdx.x;
    float ap = g_avgp[k] * (1.0f / (float)Nv);
    float v = -ap * __logf(ap + 1e-5f);
    for (int o = 16; o; o >>= 1) v += __shfl_xor_sync(~0u, v, o);
    __shared__ float ws[8];
    if ((threadIdx.x & 31) == 0) ws[threadIdx.x >> 5] = v;
    __syncthreads();
    if (threadIdx.x == 0) {
        float t = 0.0f;
        for (int w = 0; w < 8; w++) t += ws[w];
        atomicAdd(&g_acc[3], t);
    }
}

// ---------------- dead code rate ----------------
__global__ void k_dead() {
    int j = threadIdx.x;
    int v = g_idx[j];
    int same = 1;
    for (int b = 1; b < Bv; b++) same &= (g_idx[b * 1024 + j] == v);
    for (int o = 16; o; o >>= 1) same += __shfl_xor_sync(~0u, same, o);
    __shared__ int ws[32];
    if ((j & 31) == 0) ws[j >> 5] = same;
    __syncthreads();
    if (j < 32) {
        int t = ws[j];
        for (int o = 16; o; o >>= 1) t += __shfl_xor_sync(~0u, t, o);
        if (j == 0) g_acc[4] = (float)t;
    }
}

// ---------------- z_q output ----------------
__global__ __launch_bounds__(256) void k_output(float* __restrict__ out) {
    __shared__ float sm[Cv][Wv + 1];
    int bh = blockIdx.x, tid = threadIdx.x;
    for (int w = 0; w < 32; ++w) {
        int n = bh * 32 + w;
        int k = g_idx[n];
        float zf = g_zf[(size_t)n * Cv + tid];
        float e  = g_emb[(size_t)k * Cv + tid];
        sm[tid][w] = zf + (e - zf);
    }
    __syncthreads();
    float* op = out + (size_t)(bh >> 5) * Cv * (Hv * Wv) + (size_t)(bh & 31) * Wv;
    for (int it = 0; it < 32; ++it) {
        int l = it * 256 + tid;
        int c = l >> 5, w = l & 31;
        op[(size_t)c * (Hv * Wv) + w] = sm[c][w];
    }
}

// ---------------- scalars + idx ----------------
__global__ void k_finalize(float* __restrict__ out, int out_size) {
    int i = blockIdx.x * blockDim.x + threadIdx.x;
    if (i < Nv && (S0 + 4 + i) < out_size) out[S0 + 4 + i] = (float)g_idx[i];
    if (i == 0 && (S0 + 3) < out_size) {
        float denom = g_acc[1];
        float vq = g_acc[0] / (256.0f * denom);
        out[S0 + 0] = vq;
        out[S0 + 1] = 0.25f * vq;
        float sample = g_acc[2] * (1.0f / (float)Nv);
        out[S0 + 2] = 0.1f * (sample - g_acc[3]);
        out[S0 + 3] = g_acc[4] * (1.0f / 1024.0f);
    }
}

extern "C" void kernel_launch(void* const* d_in, const int* in_sizes, int n_in,
                              void* d_out, int out_size) {
    const float* z   = (const float*)d_in[0];
    const float* emb = (const float*)d_in[1];
    const void*  q   = d_in[2];
    float* out = (float*)d_out;

    cudaFuncSetAttribute(k_mma, cudaFuncAttributeMaxDynamicSharedMemorySize, SM_TOTAL);

    k_init<<<64, 256>>>(q);
    k_norm_z<<<Bv * Hv, 256>>>(z);
    k_norm_emb<<<Ev, 256>>>(emb);
    dim3 gg(Ev / BN, Nv / BM);    // 128 x 128 tiles
    k_mma<<<gg, 256, SM_TOTAL>>>();
    k_rowstats<<<Nv, 256>>>();
    dim3 gc(Ev / 256, Nv / 512);
    k_colsum<<<gc, 256>>>();
    k_avgent<<<Ev / 256, 256>>>();
    k_dead<<<1, 1024>>>();
    k_output<<<Bv * Hv, 256>>>(out);
    k_finalize<<<64, 256>>>(out, out_size);
}

// round 15
// speedup vs baseline: 2.8647x; 1.2755x over previous
#include <cuda_runtime.h>
#include <cuda_bf16.h>
#include <cuda_fp16.h>
#include <math.h>
#include <stdint.h>

// Problem dims (fixed)
#define Bv   16
#define Cv   256
#define Hv   32
#define Wv   32
#define Nv   16384
#define Ev   16384
#define S0   4194304

// GEMM tiling — single fp16 term (exact refine absorbs the rounding)
#define KBIG 256
#define BM   128
#define BN   128
#define BK   32
#define NKT  (KBIG / BK)    // 8
#define ROWB 80
#define STG  (2 * BM * ROWB)        // 20480
#define SM_TOTAL (3 * STG)          // 61440

#define CAND_EPS 0.15f
#define MAXCAND 32
#define NTILE (Ev / BN)     // 128 column tiles per row

// ---------------- device scratch (static, no allocs) ----------------
__device__ float              g_zf[(size_t)Nv * Cv];
__device__ float              g_cn[Nv];
__device__ float              g_emb[(size_t)Ev * Cv];
__device__ float              g_sk[Ev];
__device__ __align__(256) __half g_abig[(size_t)Nv * KBIG];
__device__ __align__(256) __half g_bbig[(size_t)Ev * KBIG];
__device__ __align__(256) __half g_e[(size_t)Nv * Ev];      // exp(t - m_tile), 0.5 GiB
__device__ float4             g_part[(size_t)Nv * NTILE];   // (m,Z,U,0) per row-tile, 32 MB
__device__ float              g_scale[(size_t)Nv * NTILE];  // e^{m_t-m}/Z, 8 MB
__device__ int                g_idx[Nv];
__device__ float              g_avgp[Ev];
__device__ int                g_q[Bv];
__device__ float              g_acc[8];

// ---------------- PTX helpers (base-target only) ----------------
__device__ __forceinline__ uint32_t smem_u32(const void* p) {
    uint32_t a;
    asm("{ .reg .u64 t; cvta.to.shared.u64 t, %1; cvt.u32.u64 %0, t; }" : "=r"(a) : "l"(p));
    return a;
}
__device__ __forceinline__ void cp16(uint32_t dst, const void* src) {
    asm volatile("cp.async.cg.shared.global [%0], [%1], 16;" :: "r"(dst), "l"(src) : "memory");
}
__device__ __forceinline__ void cp_commit() {
    asm volatile("cp.async.commit_group;" ::: "memory");
}
template <int N>
__device__ __forceinline__ void cp_wait() {
    asm volatile("cp.async.wait_group %0;" :: "n"(N) : "memory");
}
__device__ __forceinline__ void ldmx4(uint32_t& r0, uint32_t& r1, uint32_t& r2, uint32_t& r3,
                                      uint32_t addr) {
    asm volatile("ldmatrix.sync.aligned.m8n8.x4.shared.b16 {%0,%1,%2,%3}, [%4];"
                 : "=r"(r0), "=r"(r1), "=r"(r2), "=r"(r3) : "r"(addr));
}
__device__ __forceinline__ void hmma(float& c0, float& c1, float& c2, float& c3,
                                     uint32_t a0, uint32_t a1, uint32_t a2, uint32_t a3,
                                     uint32_t b0, uint32_t b1) {
    asm volatile(
        "mma.sync.aligned.m16n8k16.row.col.f32.f16.f16.f32 "
        "{%0,%1,%2,%3}, {%4,%5,%6,%7}, {%8,%9}, {%0,%1,%2,%3};"
        : "+f"(c0), "+f"(c1), "+f"(c2), "+f"(c3)
        : "r"(a0), "r"(a1), "r"(a2), "r"(a3), "r"(b0), "r"(b1));
}

// ---------------- init ----------------
__global__ void k_init(const void* qraw) {
    int i = blockIdx.x * blockDim.x + threadIdx.x;
    if (i < Ev) g_avgp[i] = 0.0f;
    if (i == 0) {
        const unsigned int* w32 = (const unsigned int*)qraw;
        bool is64 = true;
        for (int b = 0; b < 8; b++) if (w32[2 * b + 1] != 0u) is64 = false;
        int s = 0;
        for (int b = 0; b < Bv; b++) {
            int q = is64 ? (int)w32[2 * b] : (int)((const int*)qraw)[b];
            g_q[b] = q;
            s += q + 1;
        }
        for (int j = 0; j < 8; j++) g_acc[j] = 0.0f;
        g_acc[1] = (float)s;
    }
}

// ---------------- normalize z + emit fp16 ----------------
__global__ __launch_bounds__(256) void k_norm_z(const float* __restrict__ z) {
    __shared__ float sm[Cv][Wv + 1];
    __shared__ float sinv[Wv];
    int bh = blockIdx.x;
    int tid = threadIdx.x;
    const float* zp = z + (size_t)(bh >> 5) * Cv * (Hv * Wv) + (size_t)(bh & 31) * Wv;
    for (int it = 0; it < 32; ++it) {
        int l = it * 256 + tid;
        int c = l >> 5, w = l & 31;
        sm[c][w] = zp[(size_t)c * (Hv * Wv) + w];
    }
    __syncthreads();
    int w = tid >> 3, part = tid & 7;
    float s = 0.0f;
    for (int c = part; c < Cv; c += 8) { float v = sm[c][w]; s += v * v; }
    s += __shfl_xor_sync(~0u, s, 1);
    s += __shfl_xor_sync(~0u, s, 2);
    s += __shfl_xor_sync(~0u, s, 4);
    if (part == 0) {
        float inv = 1.0f / fmaxf(sqrtf(s), 1e-12f);
        sinv[w] = inv;
        g_cn[bh * 32 + w] = s * inv * inv;
    }
    __syncthreads();
    for (int w2 = 0; w2 < 32; ++w2) {
        int n = bh * 32 + w2;
        float v = sm[tid][w2] * sinv[w2];
        g_zf[(size_t)n * Cv + tid] = v;
        g_abig[(size_t)n * KBIG + tid] = __float2half(v);
    }
}

// ---------------- normalize embedding + emit fp16 ----------------
__global__ __launch_bounds__(256) void k_norm_emb(const float* __restrict__ e) {
    int k = blockIdx.x, tid = threadIdx.x;
    float v = e[(size_t)k * Cv + tid];
    float s = v * v;
    for (int o = 16; o; o >>= 1) s += __shfl_xor_sync(~0u, s, o);
    __shared__ float ws[8];
    if ((tid & 31) == 0) ws[tid >> 5] = s;
    __syncthreads();
    if (tid < 8) {
        float t = ws[tid];
        for (int o = 4; o; o >>= 1) t += __shfl_xor_sync(0xffu, t, o);
        if (tid == 0) ws[0] = t;
    }
    __syncthreads();
    float tot = ws[0];
    float inv = 1.0f / fmaxf(sqrtf(tot), 1e-12f);
    float vn = v * inv;
    g_emb[(size_t)k * Cv + tid] = vn;
    if (tid == 0) g_sk[k] = tot * inv * inv;
    g_bbig[(size_t)k * KBIG + tid] = __float2half(vn);
}

// ---------------- HMMA GEMM + fused softmax-partial epilogue ----------------
__device__ __forceinline__ void load_stage(uint32_t sbase, int s, const char* Ab,
                                           const char* Bb, int kt, int tid) {
    uint32_t base = sbase + s * STG;
    const char* Asrc = Ab + kt * (BK * 2);
#pragma unroll
    for (int i = 0; i < 2; i++) {
        int u = tid + i * 256;
        int r = u >> 2, c = u & 3;
        cp16(base + r * ROWB + c * 16, Asrc + (size_t)r * (KBIG * 2) + c * 16);
    }
    uint32_t bbase = base + BM * ROWB;
    const char* Bsrc = Bb + kt * (BK * 2);
#pragma unroll
    for (int i = 0; i < 2; i++) {
        int u = tid + i * 256;
        int r = u >> 2, c = u & 3;
        cp16(bbase + r * ROWB + c * 16, Bsrc + (size_t)r * (KBIG * 2) + c * 16);
    }
}

__global__ void __launch_bounds__(256, 2) k_mma() {
    extern __shared__ char smem[];
    uint32_t sbase = smem_u32(smem);
    int tid = threadIdx.x, wid = tid >> 5, lane = tid & 31;
    int g = lane >> 2, tig = lane & 3;
    int warpM = wid >> 2, warpN = wid & 3;          // 2 x 4
    int bm = blockIdx.y * BM, bn = blockIdx.x * BN;

    const char* Ab = (const char*)g_abig + (size_t)bm * (KBIG * 2);
    const char* Bb = (const char*)g_bbig + (size_t)bn * (KBIG * 2);

    int aoff = ((((lane >> 3) & 1) * 8 + (lane & 7)) * ROWB) + ((lane >> 4) * 16);
    int boff = ((((lane >> 4) & 1) * 8 + (lane & 7)) * ROWB) + (((lane >> 3) & 1) * 16);
    uint32_t abase = sbase + (warpM * 64) * ROWB + aoff;
    uint32_t bbase = sbase + BM * ROWB + (warpN * 32) * ROWB + boff;

    float acc[4][4][4];
#pragma unroll
    for (int mi = 0; mi < 4; mi++)
#pragma unroll
        for (int ni = 0; ni < 4; ni++)
#pragma unroll
            for (int r = 0; r < 4; r++) acc[mi][ni][r] = 0.0f;

    load_stage(sbase, 0, Ab, Bb, 0, tid); cp_commit();
    load_stage(sbase, 1, Ab, Bb, 1, tid); cp_commit();

    for (int kt = 0; kt < NKT; kt++) {
        cp_wait<1>();
        __syncthreads();
        if (kt + 2 < NKT) load_stage(sbase, (kt + 2) % 3, Ab, Bb, kt + 2, tid);
        cp_commit();

        uint32_t stg = (uint32_t)((kt % 3) * STG);
#pragma unroll
        for (int k16 = 0; k16 < 2; k16++) {
            uint32_t koff = k16 * 32;
            uint32_t Ar[4][4], Br[4][2];
#pragma unroll
            for (int mi = 0; mi < 4; mi++)
                ldmx4(Ar[mi][0], Ar[mi][1], Ar[mi][2], Ar[mi][3],
                      abase + stg + mi * 16 * ROWB + koff);
#pragma unroll
            for (int nip = 0; nip < 2; nip++)
                ldmx4(Br[2 * nip][0], Br[2 * nip][1], Br[2 * nip + 1][0], Br[2 * nip + 1][1],
                      bbase + stg + nip * 16 * ROWB + koff);
#pragma unroll
            for (int mi = 0; mi < 4; mi++)
#pragma unroll
                for (int ni = 0; ni < 4; ni++)
                    hmma(acc[mi][ni][0], acc[mi][ni][1], acc[mi][ni][2], acc[mi][ni][3],
                         Ar[mi][0], Ar[mi][1], Ar[mi][2], Ar[mi][3],
                         Br[ni][0], Br[ni][1]);
        }
        __syncthreads();
    }

    // ---- epilogue: t in place, per-(row,tile) m/Z/U partials, e -> fp16 ----
    float* smf = (float*)smem;  // [0..511] m, [512..1023] Z, [1024..1535] U
    int colb = bn + warpN * 32;
    int rbase = warpM * 64 + g;   // + mi*16 + h*8  (local row)
    float skv[4][2];
#pragma unroll
    for (int ni = 0; ni < 4; ni++) {
        int c0 = colb + ni * 8 + 2 * tig;
        skv[ni][0] = __ldg(&g_sk[c0]);
        skv[ni][1] = __ldg(&g_sk[c0 + 1]);
    }
    // t = 200*G - 100*sk, and thread-local max per (mi,h)
    float lm[4][2];
#pragma unroll
    for (int mi = 0; mi < 4; mi++) {
        lm[mi][0] = -3.4e38f; lm[mi][1] = -3.4e38f;
#pragma unroll
        for (int ni = 0; ni < 4; ni++) {
            acc[mi][ni][0] = 200.0f * acc[mi][ni][0] - 100.0f * skv[ni][0];
            acc[mi][ni][1] = 200.0f * acc[mi][ni][1] - 100.0f * skv[ni][1];
            acc[mi][ni][2] = 200.0f * acc[mi][ni][2] - 100.0f * skv[ni][0];
            acc[mi][ni][3] = 200.0f * acc[mi][ni][3] - 100.0f * skv[ni][1];
            lm[mi][0] = fmaxf(lm[mi][0], fmaxf(acc[mi][ni][0], acc[mi][ni][1]));
            lm[mi][1] = fmaxf(lm[mi][1], fmaxf(acc[mi][ni][2], acc[mi][ni][3]));
        }
    }
#pragma unroll
    for (int mi = 0; mi < 4; mi++)
#pragma unroll
        for (int h = 0; h < 2; h++) {
            lm[mi][h] = fmaxf(lm[mi][h], __shfl_xor_sync(~0u, lm[mi][h], 1));
            lm[mi][h] = fmaxf(lm[mi][h], __shfl_xor_sync(~0u, lm[mi][h], 2));
        }
    if (tig == 0) {
#pragma unroll
        for (int mi = 0; mi < 4; mi++)
#pragma unroll
            for (int h = 0; h < 2; h++)
                smf[(rbase + mi * 16 + h * 8) * 4 + warpN] = lm[mi][h];
    }
    __syncthreads();
    float mt[4][2];
#pragma unroll
    for (int mi = 0; mi < 4; mi++)
#pragma unroll
        for (int h = 0; h < 2; h++) {
            int r4 = (rbase + mi * 16 + h * 8) * 4;
            mt[mi][h] = fmaxf(fmaxf(smf[r4], smf[r4 + 1]), fmaxf(smf[r4 + 2], smf[r4 + 3]));
        }
    float zl[4][2], ul[4][2];
#pragma unroll
    for (int mi = 0; mi < 4; mi++) { zl[mi][0] = zl[mi][1] = 0.0f; ul[mi][0] = ul[mi][1] = 0.0f; }
#pragma unroll
    for (int mi = 0; mi < 4; mi++) {
        size_t r0 = (size_t)(bm + rbase + mi * 16);
        __half* e0 = g_e + r0 * Ev;
        __half* e1 = g_e + (r0 + 8) * Ev;
#pragma unroll
        for (int ni = 0; ni < 4; ni++) {
            int c0 = colb + ni * 8 + 2 * tig;
            float u00 = acc[mi][ni][0] - mt[mi][0];
            float u01 = acc[mi][ni][1] - mt[mi][0];
            float u10 = acc[mi][ni][2] - mt[mi][1];
            float u11 = acc[mi][ni][3] - mt[mi][1];
            float e00 = __expf(u00), e01 = __expf(u01);
            float e10 = __expf(u10), e11 = __expf(u11);
            *(__half2*)(e0 + c0) = __floats2half2_rn(e00, e01);
            *(__half2*)(e1 + c0) = __floats2half2_rn(e10, e11);
            zl[mi][0] += e00 + e01;
            zl[mi][1] += e10 + e11;
            ul[mi][0] += e00 * u00 + e01 * u01;
            ul[mi][1] += e10 * u10 + e11 * u11;
        }
    }
#pragma unroll
    for (int mi = 0; mi < 4; mi++)
#pragma unroll
        for (int h = 0; h < 2; h++) {
            zl[mi][h] += __shfl_xor_sync(~0u, zl[mi][h], 1);
            zl[mi][h] += __shfl_xor_sync(~0u, zl[mi][h], 2);
            ul[mi][h] += __shfl_xor_sync(~0u, ul[mi][h], 1);
            ul[mi][h] += __shfl_xor_sync(~0u, ul[mi][h], 2);
        }
    if (tig == 0) {
#pragma unroll
        for (int mi = 0; mi < 4; mi++)
#pragma unroll
            for (int h = 0; h < 2; h++) {
                int r = rbase + mi * 16 + h * 8;
                smf[512 + r * 4 + warpN] = zl[mi][h];
                smf[1024 + r * 4 + warpN] = ul[mi][h];
            }
    }
    __syncthreads();
    if (warpN == 0 && tig == 0) {
#pragma unroll
        for (int mi = 0; mi < 4; mi++)
#pragma unroll
            for (int h = 0; h < 2; h++) {
                int r = rbase + mi * 16 + h * 8;
                float Z = smf[512 + r * 4] + smf[512 + r * 4 + 1] + smf[512 + r * 4 + 2] + smf[512 + r * 4 + 3];
                float U = smf[1024 + r * 4] + smf[1024 + r * 4 + 1] + smf[1024 + r * 4 + 2] + smf[1024 + r * 4 + 3];
                g_part[(size_t)(bm + r) * NTILE + blockIdx.x] = make_float4(mt[mi][h], Z, U, 0.0f);
            }
    }
}

// ---------------- row reduce: merge partials, exact refine, scales ----------------
__global__ __launch_bounds__(128) void k_rowred() {
    int n = blockIdx.x, tid = threadIdx.x, wid = tid >> 5, lane = tid & 31;
    __shared__ float wred[4];
    __shared__ int s_cand[MAXCAND];
    __shared__ int s_cnt;
    __shared__ int s_bidx;
    __shared__ float s_bt;
    if (tid == 0) { s_cnt = 0; s_bidx = 0; s_bt = -3.4e38f; }

    float4 p = g_part[(size_t)n * NTILE + tid];
    float mi = p.x, Zi = p.y, Ui = p.z;

    float m = mi;
    for (int o = 16; o; o >>= 1) m = fmaxf(m, __shfl_xor_sync(~0u, m, o));
    if (lane == 0) wred[wid] = m;
    __syncthreads();
    m = fmaxf(fmaxf(wred[0], wred[1]), fmaxf(wred[2], wred[3]));
    __syncthreads();

    float li = __expf(mi - m);
    float Zc = Zi * li;
    float Uc = fmaf(mi - m, Zi, Ui) * li;
    float zs = Zc;
    for (int o = 16; o; o >>= 1) zs += __shfl_xor_sync(~0u, zs, o);
    if (lane == 0) wred[wid] = zs;
    __syncthreads();
    float Z = wred[0] + wred[1] + wred[2] + wred[3];
    __syncthreads();
    float us = Uc;
    for (int o = 16; o; o >>= 1) us += __shfl_xor_sync(~0u, us, o);
    if (lane == 0) wred[wid] = us;
    __syncthreads();
    float U = wred[0] + wred[1] + wred[2] + wred[3];

    g_scale[(size_t)n * NTILE + tid] = li / Z;

    // candidate columns from flagged tiles
    if (mi > m - CAND_EPS) {
        const __half* ep = g_e + (size_t)n * Ev + tid * BN;
        float thr = __expf((m - CAND_EPS) - mi);
        for (int j = 0; j < BN; j++) {
            if (__half2float(ep[j]) > thr) {
                int q = atomicAdd(&s_cnt, 1);
                if (q < MAXCAND) s_cand[q] = tid * BN + j;
            }
        }
    }
    __syncthreads();
    int nc = min(s_cnt, MAXCAND);
    if (tid < 32) {
        float bt = -3.4e38f; int bc = 0x7fffffff;
        if (tid < nc) {
            int k = s_cand[tid];
            const float* ap = g_zf + (size_t)n * Cv;
            const float* bp = g_emb + (size_t)k * Cv;
            float dot = 0.0f;
#pragma unroll 8
            for (int c = 0; c < Cv; c++) dot = fmaf(__ldg(ap + c), __ldg(bp + c), dot);
            bt = 200.0f * dot - 100.0f * __ldg(&g_sk[k]);
            bc = k;
        }
#pragma unroll
        for (int o = 1; o < 32; o <<= 1) {
            float ov = __shfl_xor_sync(~0u, bt, o);
            int   oc = __shfl_xor_sync(~0u, bc, o);
            if (ov > bt || (ov == bt && oc < bc)) { bt = ov; bc = oc; }
        }
        if (tid == 0) { s_bidx = bc; s_bt = bt; }
    }
    __syncthreads();
    if (tid == 0) {
        g_idx[n] = s_bidx;
        atomicAdd(&g_acc[2], __logf(Z) - U / Z);
        float dmin = g_cn[n] - 0.01f * s_bt;
        int b = n >> 10, w = n & 31;
        if (w <= g_q[b]) atomicAdd(&g_acc[0], dmin);
    }
}

// ---------------- column pass: avg_probs from fp16 e, no exps ----------------
__global__ __launch_bounds__(256) void k_colsum() {
    __shared__ float s_s[512][2];
    int tid = threadIdx.x;
    int bx = blockIdx.x;
    int n0 = blockIdx.y * 512;
    int t0 = 2 * bx;
    for (int i = tid; i < 512; i += 256) {
        s_s[i][0] = g_scale[(size_t)(n0 + i) * NTILE + t0];
        s_s[i][1] = g_scale[(size_t)(n0 + i) * NTILE + t0 + 1];
    }
    __syncthreads();
    int col = bx * 256 + tid;
    int sel = tid >> 7;
    const __half* ep = g_e + col;
    float acc = 0.0f;
#pragma unroll 8
    for (int i = 0; i < 512; i++)
        acc = fmaf(__half2float(ep[(size_t)(n0 + i) * Ev]), s_s[i][sel], acc);
    atomicAdd(&g_avgp[col], acc);
}

// ---------------- avg entropy ----------------
__global__ __launch_bounds__(256) void k_avgent() {
    int k = blockIdx.x * 256 + threadIdx.x;
    float ap = g_avgp[k] * (1.0f / (float)Nv);
    float v = -ap * __logf(ap + 1e-5f);
    for (int o = 16; o; o >>= 1) v += __shfl_xor_sync(~0u, v, o);
    __shared__ float ws[8];
    if ((threadIdx.x & 31) == 0) ws[threadIdx.x >> 5] = v;
    __syncthreads();
    if (threadIdx.x == 0) {
        float t = 0.0f;
        for (int w = 0; w < 8; w++) t += ws[w];
        atomicAdd(&g_acc[3], t);
    }
}

// ---------------- dead code rate ----------------
__global__ void k_dead() {
    int j = threadIdx.x;
    int v = g_idx[j];
    int same = 1;
    for (int b = 1; b < Bv; b++) same &= (g_idx[b * 1024 + j] == v);
    for (int o = 16; o; o >>= 1) same += __shfl_xor_sync(~0u, same, o);
    __shared__ int ws[32];
    if ((j & 31) == 0) ws[j >> 5] = same;
    __syncthreads();
    if (j < 32) {
        int t = ws[j];
        for (int o = 16; o; o >>= 1) t += __shfl_xor_sync(~0u, t, o);
        if (j == 0) g_acc[4] = (float)t;
    }
}

// ---------------- z_q output ----------------
__global__ __launch_bounds__(256) void k_output(float* __restrict__ out) {
    __shared__ float sm[Cv][Wv + 1];
    int bh = blockIdx.x, tid = threadIdx.x;
    for (int w = 0; w < 32; ++w) {
        int n = bh * 32 + w;
        int k = g_idx[n];
        float zf = g_zf[(size_t)n * Cv + tid];
        float e  = g_emb[(size_t)k * Cv + tid];
        sm[tid][w] = zf + (e - zf);
    }
    __syncthreads();
    float* op = out + (size_t)(bh >> 5) * Cv * (Hv * Wv) + (size_t)(bh & 31) * Wv;
    for (int it = 0; it < 32; ++it) {
        int l = it * 256 + tid;
        int c = l >> 5, w = l & 31;
        op[(size_t)c * (Hv * Wv) + w] = sm[c][w];
    }
}

// ---------------- scalars + idx ----------------
__global__ void k_finalize(float* __restrict__ out, int out_size) {
    int i = blockIdx.x * blockDim.x + threadIdx.x;
    if (i < Nv && (S0 + 4 + i) < out_size) out[S0 + 4 + i] = (float)g_idx[i];
    if (i == 0 && (S0 + 3) < out_size) {
        float denom = g_acc[1];
        float vq = g_acc[0] / (256.0f * denom);
        out[S0 + 0] = vq;
        out[S0 + 1] = 0.25f * vq;
        float sample = g_acc[2] * (1.0f / (float)Nv);
        out[S0 + 2] = 0.1f * (sample - g_acc[3]);
        out[S0 + 3] = g_acc[4] * (1.0f / 1024.0f);
    }
}

extern "C" void kernel_launch(void* const* d_in, const int* in_sizes, int n_in,
                              void* d_out, int out_size) {
    const float* z   = (const float*)d_in[0];
    const float* emb = (const float*)d_in[1];
    const void*  q   = d_in[2];
    float* out = (float*)d_out;

    cudaFuncSetAttribute(k_mma, cudaFuncAttributeMaxDynamicSharedMemorySize, SM_TOTAL);

    k_init<<<64, 256>>>(q);
    k_norm_z<<<Bv * Hv, 256>>>(z);
    k_norm_emb<<<Ev, 256>>>(emb);
    dim3 gg(Ev / BN, Nv / BM);
    k_mma<<<gg, 256, SM_TOTAL>>>();
    k_rowred<<<Nv, 128>>>();
    dim3 gc(Ev / 256, Nv / 512);
    k_colsum<<<gc, 256>>>();
    k_avgent<<<Ev / 256, 256>>>();
    k_dead<<<1, 1024>>>();
    k_output<<<Bv * Hv, 256>>>(out);
    k_finalize<<<64, 256>>>(out, out_size);
}

// round 16
// speedup vs baseline: 3.1323x; 1.0934x over previous
#include <cuda_runtime.h>
#include <cuda_bf16.h>
#include <cuda_fp16.h>
#include <math.h>
#include <stdint.h>

// Problem dims (fixed)
#define Bv   16
#define Cv   256
#define Hv   32
#define Wv   32
#define Nv   16384
#define Ev   16384
#define S0   4194304

// GEMM tiling — single fp16 term, A-resident, 2 N-subtiles per block
#define KBIG 256
#define BM   128
#define BN   128
#define BNBIG 256
#define NSUB 2
#define BK   32
#define NKT  (KBIG / BK)    // 8
#define ROWA 528            // A row stride (512 data + 16 pad), conflict-free
#define ROWB 80
#define A_BYTES (BM * ROWA)          // 67584
#define BSTG (BM * ROWB)             // 10240
#define SMF_OFF (A_BYTES + 3 * BSTG) // 98304
#define SM_TOTAL (SMF_OFF + 6144)    // 104448

#define CAND_EPS 0.15f
#define MAXCAND 32
#define NTILE (Ev / BN)     // 128

// ---------------- device scratch (static, no allocs) ----------------
__device__ float              g_zf[(size_t)Nv * Cv];
__device__ float              g_cn[Nv];
__device__ float              g_emb[(size_t)Ev * Cv];
__device__ float              g_sk[Ev];
__device__ __align__(256) __half g_abig[(size_t)Nv * KBIG];
__device__ __align__(256) __half g_bbig[(size_t)Ev * KBIG];
__device__ __align__(256) __half g_e[(size_t)Nv * Ev];      // exp(t - m_tile), 0.5 GiB
__device__ float4             g_part[(size_t)Nv * NTILE];   // (m,Z,U,0) per row-tile
__device__ float              g_scale[(size_t)Nv * NTILE];  // e^{m_t-m}/Z
__device__ int                g_idx[Nv];
__device__ float              g_avgp[Ev];
__device__ int                g_q[Bv];
__device__ float              g_acc[8];

// ---------------- PTX helpers (base-target only) ----------------
__device__ __forceinline__ uint32_t smem_u32(const void* p) {
    uint32_t a;
    asm("{ .reg .u64 t; cvta.to.shared.u64 t, %1; cvt.u32.u64 %0, t; }" : "=r"(a) : "l"(p));
    return a;
}
__device__ __forceinline__ void cp16(uint32_t dst, const void* src) {
    asm volatile("cp.async.cg.shared.global [%0], [%1], 16;" :: "r"(dst), "l"(src) : "memory");
}
__device__ __forceinline__ void cp_commit() {
    asm volatile("cp.async.commit_group;" ::: "memory");
}
template <int N>
__device__ __forceinline__ void cp_wait() {
    asm volatile("cp.async.wait_group %0;" :: "n"(N) : "memory");
}
__device__ __forceinline__ void ldmx4(uint32_t& r0, uint32_t& r1, uint32_t& r2, uint32_t& r3,
                                      uint32_t addr) {
    asm volatile("ldmatrix.sync.aligned.m8n8.x4.shared.b16 {%0,%1,%2,%3}, [%4];"
                 : "=r"(r0), "=r"(r1), "=r"(r2), "=r"(r3) : "r"(addr));
}
__device__ __forceinline__ void hmma(float& c0, float& c1, float& c2, float& c3,
                                     uint32_t a0, uint32_t a1, uint32_t a2, uint32_t a3,
                                     uint32_t b0, uint32_t b1) {
    asm volatile(
        "mma.sync.aligned.m16n8k16.row.col.f32.f16.f16.f32 "
        "{%0,%1,%2,%3}, {%4,%5,%6,%7}, {%8,%9}, {%0,%1,%2,%3};"
        : "+f"(c0), "+f"(c1), "+f"(c2), "+f"(c3)
        : "r"(a0), "r"(a1), "r"(a2), "r"(a3), "r"(b0), "r"(b1));
}

// ---------------- init ----------------
__global__ void k_init(const void* qraw) {
    int i = blockIdx.x * blockDim.x + threadIdx.x;
    if (i < Ev) g_avgp[i] = 0.0f;
    if (i == 0) {
        const unsigned int* w32 = (const unsigned int*)qraw;
        bool is64 = true;
        for (int b = 0; b < 8; b++) if (w32[2 * b + 1] != 0u) is64 = false;
        int s = 0;
        for (int b = 0; b < Bv; b++) {
            int q = is64 ? (int)w32[2 * b] : (int)((const int*)qraw)[b];
            g_q[b] = q;
            s += q + 1;
        }
        for (int j = 0; j < 8; j++) g_acc[j] = 0.0f;
        g_acc[1] = (float)s;
    }
}

// ---------------- normalize z + emit fp16 ----------------
__global__ __launch_bounds__(256) void k_norm_z(const float* __restrict__ z) {
    __shared__ float sm[Cv][Wv + 1];
    __shared__ float sinv[Wv];
    int bh = blockIdx.x;
    int tid = threadIdx.x;
    const float* zp = z + (size_t)(bh >> 5) * Cv * (Hv * Wv) + (size_t)(bh & 31) * Wv;
    for (int it = 0; it < 32; ++it) {
        int l = it * 256 + tid;
        int c = l >> 5, w = l & 31;
        sm[c][w] = zp[(size_t)c * (Hv * Wv) + w];
    }
    __syncthreads();
    int w = tid >> 3, part = tid & 7;
    float s = 0.0f;
    for (int c = part; c < Cv; c += 8) { float v = sm[c][w]; s += v * v; }
    s += __shfl_xor_sync(~0u, s, 1);
    s += __shfl_xor_sync(~0u, s, 2);
    s += __shfl_xor_sync(~0u, s, 4);
    if (part == 0) {
        float inv = 1.0f / fmaxf(sqrtf(s), 1e-12f);
        sinv[w] = inv;
        g_cn[bh * 32 + w] = s * inv * inv;
    }
    __syncthreads();
    for (int w2 = 0; w2 < 32; ++w2) {
        int n = bh * 32 + w2;
        float v = sm[tid][w2] * sinv[w2];
        g_zf[(size_t)n * Cv + tid] = v;
        g_abig[(size_t)n * KBIG + tid] = __float2half(v);
    }
}

// ---------------- normalize embedding + emit fp16 ----------------
__global__ __launch_bounds__(256) void k_norm_emb(const float* __restrict__ e) {
    int k = blockIdx.x, tid = threadIdx.x;
    float v = e[(size_t)k * Cv + tid];
    float s = v * v;
    for (int o = 16; o; o >>= 1) s += __shfl_xor_sync(~0u, s, o);
    __shared__ float ws[8];
    if ((tid & 31) == 0) ws[tid >> 5] = s;
    __syncthreads();
    if (tid < 8) {
        float t = ws[tid];
        for (int o = 4; o; o >>= 1) t += __shfl_xor_sync(0xffu, t, o);
        if (tid == 0) ws[0] = t;
    }
    __syncthreads();
    float tot = ws[0];
    float inv = 1.0f / fmaxf(sqrtf(tot), 1e-12f);
    float vn = v * inv;
    g_emb[(size_t)k * Cv + tid] = vn;
    if (tid == 0) g_sk[k] = tot * inv * inv;
    g_bbig[(size_t)k * KBIG + tid] = __float2half(vn);
}

// ---------------- HMMA GEMM (A-resident, 2 N-subtiles) + fused softmax epilogue ----------------
__device__ __forceinline__ void load_B(uint32_t sbase, int s, const char* Bb, int kt, int tid) {
    uint32_t base = sbase + A_BYTES + s * BSTG;
    const char* src = Bb + kt * (BK * 2);
#pragma unroll
    for (int i = 0; i < 2; i++) {
        int u = tid + i * 256;
        int r = u >> 2, c = (u & 3) * 16;
        cp16(base + r * ROWB + c, src + (size_t)r * (KBIG * 2) + c);
    }
}

__global__ void __launch_bounds__(256, 2) k_mma() {
    extern __shared__ char smem[];
    uint32_t sbase = smem_u32(smem);
    int tid = threadIdx.x, wid = tid >> 5, lane = tid & 31;
    int g = lane >> 2, tig = lane & 3;
    int warpM = wid >> 2, warpN = wid & 3;          // 2 x 4
    int bm = blockIdx.y * BM, bn0 = blockIdx.x * BNBIG;

    const char* Ab = (const char*)g_abig + (size_t)bm * (KBIG * 2);

    // full A tile resident: 128 rows x 512 B
    {
#pragma unroll
        for (int i = 0; i < 16; i++) {
            int u = tid + i * 256;
            int r = u >> 5, c = (u & 31) * 16;
            cp16(sbase + r * ROWA + c, Ab + (size_t)r * (KBIG * 2) + c);
        }
        cp_commit();
    }
    // preload B stages 0,1 for subtile 0
    {
        const char* Bb0 = (const char*)g_bbig + (size_t)bn0 * (KBIG * 2);
        load_B(sbase, 0, Bb0, 0, tid); cp_commit();
        load_B(sbase, 1, Bb0, 1, tid); cp_commit();
    }

    int aoffA = ((((lane >> 3) & 1) * 8 + (lane & 7)) * ROWA) + ((lane >> 4) * 16);
    int boff  = ((((lane >> 4) & 1) * 8 + (lane & 7)) * ROWB) + (((lane >> 3) & 1) * 16);
    uint32_t abase = sbase + (warpM * 64) * ROWA + aoffA;
    uint32_t bwarp = sbase + A_BYTES + (warpN * 32) * ROWB + boff;
    int rbase = warpM * 64 + g;
    float* smf = (float*)(smem + SMF_OFF);

    for (int sub = 0; sub < NSUB; sub++) {
        int bn = bn0 + sub * BM;
        const char* Bb = (const char*)g_bbig + (size_t)bn * (KBIG * 2);

        float acc[4][4][4];
#pragma unroll
        for (int mi = 0; mi < 4; mi++)
#pragma unroll
            for (int ni = 0; ni < 4; ni++)
#pragma unroll
                for (int r = 0; r < 4; r++) acc[mi][ni][r] = 0.0f;

        for (int kt = 0; kt < NKT; kt++) {
            cp_wait<1>();
            __syncthreads();
            if (kt + 2 < NKT) load_B(sbase, (kt + 2) % 3, Bb, kt + 2, tid);
            cp_commit();

            uint32_t bstg = bwarp + (uint32_t)((kt % 3) * BSTG);
            uint32_t akt = abase + kt * (BK * 2);
#pragma unroll
            for (int k16 = 0; k16 < 2; k16++) {
                uint32_t koff = k16 * 32;
                uint32_t Ar[4][4], Br[4][2];
#pragma unroll
                for (int mi = 0; mi < 4; mi++)
                    ldmx4(Ar[mi][0], Ar[mi][1], Ar[mi][2], Ar[mi][3],
                          akt + mi * 16 * ROWA + koff);
#pragma unroll
                for (int nip = 0; nip < 2; nip++)
                    ldmx4(Br[2 * nip][0], Br[2 * nip][1], Br[2 * nip + 1][0], Br[2 * nip + 1][1],
                          bstg + nip * 16 * ROWB + koff);
#pragma unroll
                for (int mi = 0; mi < 4; mi++)
#pragma unroll
                    for (int ni = 0; ni < 4; ni++)
                        hmma(acc[mi][ni][0], acc[mi][ni][1], acc[mi][ni][2], acc[mi][ni][3],
                             Ar[mi][0], Ar[mi][1], Ar[mi][2], Ar[mi][3],
                             Br[ni][0], Br[ni][1]);
            }
            __syncthreads();
        }

        // kick off next subtile's B prefetch before the epilogue (overlap)
        if (sub + 1 < NSUB) {
            const char* Bb1 = (const char*)g_bbig + (size_t)(bn0 + (sub + 1) * BM) * (KBIG * 2);
            load_B(sbase, 0, Bb1, 0, tid); cp_commit();
            load_B(sbase, 1, Bb1, 1, tid); cp_commit();
        }

        // ---- epilogue: t, per-(row,tile) m/Z/U partials, e -> fp16 ----
        int colb = bn + warpN * 32;
        float skv[4][2];
#pragma unroll
        for (int ni = 0; ni < 4; ni++) {
            int c0 = colb + ni * 8 + 2 * tig;
            skv[ni][0] = __ldg(&g_sk[c0]);
            skv[ni][1] = __ldg(&g_sk[c0 + 1]);
        }
        float lm[4][2];
#pragma unroll
        for (int mi = 0; mi < 4; mi++) {
            lm[mi][0] = -3.4e38f; lm[mi][1] = -3.4e38f;
#pragma unroll
            for (int ni = 0; ni < 4; ni++) {
                acc[mi][ni][0] = 200.0f * acc[mi][ni][0] - 100.0f * skv[ni][0];
                acc[mi][ni][1] = 200.0f * acc[mi][ni][1] - 100.0f * skv[ni][1];
                acc[mi][ni][2] = 200.0f * acc[mi][ni][2] - 100.0f * skv[ni][0];
                acc[mi][ni][3] = 200.0f * acc[mi][ni][3] - 100.0f * skv[ni][1];
                lm[mi][0] = fmaxf(lm[mi][0], fmaxf(acc[mi][ni][0], acc[mi][ni][1]));
                lm[mi][1] = fmaxf(lm[mi][1], fmaxf(acc[mi][ni][2], acc[mi][ni][3]));
            }
        }
#pragma unroll
        for (int mi = 0; mi < 4; mi++)
#pragma unroll
            for (int h = 0; h < 2; h++) {
                lm[mi][h] = fmaxf(lm[mi][h], __shfl_xor_sync(~0u, lm[mi][h], 1));
                lm[mi][h] = fmaxf(lm[mi][h], __shfl_xor_sync(~0u, lm[mi][h], 2));
            }
        if (tig == 0) {
#pragma unroll
            for (int mi = 0; mi < 4; mi++)
#pragma unroll
                for (int h = 0; h < 2; h++)
                    smf[(rbase + mi * 16 + h * 8) * 4 + warpN] = lm[mi][h];
        }
        __syncthreads();
        float mt[4][2];
#pragma unroll
        for (int mi = 0; mi < 4; mi++)
#pragma unroll
            for (int h = 0; h < 2; h++) {
                int r4 = (rbase + mi * 16 + h * 8) * 4;
                mt[mi][h] = fmaxf(fmaxf(smf[r4], smf[r4 + 1]), fmaxf(smf[r4 + 2], smf[r4 + 3]));
            }
        float zl[4][2], ul[4][2];
#pragma unroll
        for (int mi = 0; mi < 4; mi++) { zl[mi][0] = zl[mi][1] = 0.0f; ul[mi][0] = ul[mi][1] = 0.0f; }
#pragma unroll
        for (int mi = 0; mi < 4; mi++) {
            size_t r0 = (size_t)(bm + rbase + mi * 16);
            __half* e0 = g_e + r0 * Ev;
            __half* e1 = g_e + (r0 + 8) * Ev;
#pragma unroll
            for (int ni = 0; ni < 4; ni++) {
                int c0 = colb + ni * 8 + 2 * tig;
                float u00 = acc[mi][ni][0] - mt[mi][0];
                float u01 = acc[mi][ni][1] - mt[mi][0];
                float u10 = acc[mi][ni][2] - mt[mi][1];
                float u11 = acc[mi][ni][3] - mt[mi][1];
                float e00 = __expf(u00), e01 = __expf(u01);
                float e10 = __expf(u10), e11 = __expf(u11);
                *(__half2*)(e0 + c0) = __floats2half2_rn(e00, e01);
                *(__half2*)(e1 + c0) = __floats2half2_rn(e10, e11);
                zl[mi][0] += e00 + e01;
                zl[mi][1] += e10 + e11;
                ul[mi][0] += e00 * u00 + e01 * u01;
                ul[mi][1] += e10 * u10 + e11 * u11;
            }
        }
#pragma unroll
        for (int mi = 0; mi < 4; mi++)
#pragma unroll
            for (int h = 0; h < 2; h++) {
                zl[mi][h] += __shfl_xor_sync(~0u, zl[mi][h], 1);
                zl[mi][h] += __shfl_xor_sync(~0u, zl[mi][h], 2);
                ul[mi][h] += __shfl_xor_sync(~0u, ul[mi][h], 1);
                ul[mi][h] += __shfl_xor_sync(~0u, ul[mi][h], 2);
            }
        if (tig == 0) {
#pragma unroll
            for (int mi = 0; mi < 4; mi++)
#pragma unroll
                for (int h = 0; h < 2; h++) {
                    int r = rbase + mi * 16 + h * 8;
                    smf[512 + r * 4 + warpN] = zl[mi][h];
                    smf[1024 + r * 4 + warpN] = ul[mi][h];
                }
        }
        __syncthreads();
        if (warpN == 0 && tig == 0) {
#pragma unroll
            for (int mi = 0; mi < 4; mi++)
#pragma unroll
                for (int h = 0; h < 2; h++) {
                    int r = rbase + mi * 16 + h * 8;
                    float Z = smf[512 + r * 4] + smf[512 + r * 4 + 1] + smf[512 + r * 4 + 2] + smf[512 + r * 4 + 3];
                    float U = smf[1024 + r * 4] + smf[1024 + r * 4 + 1] + smf[1024 + r * 4 + 2] + smf[1024 + r * 4 + 3];
                    g_part[(size_t)(bm + r) * NTILE + (blockIdx.x * NSUB + sub)] =
                        make_float4(mt[mi][h], Z, U, 0.0f);
                }
        }
    }
}

// ---------------- row reduce: merge partials, exact refine, scales ----------------
__global__ __launch_bounds__(128) void k_rowred() {
    int n = blockIdx.x, tid = threadIdx.x, wid = tid >> 5, lane = tid & 31;
    __shared__ float wred[4];
    __shared__ int s_cand[MAXCAND];
    __shared__ int s_cnt;
    __shared__ int s_bidx;
    __shared__ float s_bt;
    if (tid == 0) { s_cnt = 0; s_bidx = 0; s_bt = -3.4e38f; }

    float4 p = g_part[(size_t)n * NTILE + tid];
    float mi = p.x, Zi = p.y, Ui = p.z;

    float m = mi;
    for (int o = 16; o; o >>= 1) m = fmaxf(m, __shfl_xor_sync(~0u, m, o));
    if (lane == 0) wred[wid] = m;
    __syncthreads();
    m = fmaxf(fmaxf(wred[0], wred[1]), fmaxf(wred[2], wred[3]));
    __syncthreads();

    float li = __expf(mi - m);
    float Zc = Zi * li;
    float Uc = fmaf(mi - m, Zi, Ui) * li;
    float zs = Zc;
    for (int o = 16; o; o >>= 1) zs += __shfl_xor_sync(~0u, zs, o);
    if (lane == 0) wred[wid] = zs;
    __syncthreads();
    float Z = wred[0] + wred[1] + wred[2] + wred[3];
    __syncthreads();
    float us = Uc;
    for (int o = 16; o; o >>= 1) us += __shfl_xor_sync(~0u, us, o);
    if (lane == 0) wred[wid] = us;
    __syncthreads();
    float U = wred[0] + wred[1] + wred[2] + wred[3];

    g_scale[(size_t)n * NTILE + tid] = li / Z;

    if (mi > m - CAND_EPS) {
        const __half* ep = g_e + (size_t)n * Ev + tid * BN;
        float thr = __expf((m - CAND_EPS) - mi);
        for (int j = 0; j < BN; j++) {
            if (__half2float(ep[j]) > thr) {
                int q = atomicAdd(&s_cnt, 1);
                if (q < MAXCAND) s_cand[q] = tid * BN + j;
            }
        }
    }
    __syncthreads();
    int nc = min(s_cnt, MAXCAND);
    if (tid < 32) {
        float bt = -3.4e38f; int bc = 0x7fffffff;
        if (tid < nc) {
            int k = s_cand[tid];
            const float* ap = g_zf + (size_t)n * Cv;
            const float* bp = g_emb + (size_t)k * Cv;
            float dot = 0.0f;
#pragma unroll 8
            for (int c = 0; c < Cv; c++) dot = fmaf(__ldg(ap + c), __ldg(bp + c), dot);
            bt = 200.0f * dot - 100.0f * __ldg(&g_sk[k]);
            bc = k;
        }
#pragma unroll
        for (int o = 1; o < 32; o <<= 1) {
            float ov = __shfl_xor_sync(~0u, bt, o);
            int   oc = __shfl_xor_sync(~0u, bc, o);
            if (ov > bt || (ov == bt && oc < bc)) { bt = ov; bc = oc; }
        }
        if (tid == 0) { s_bidx = bc; s_bt = bt; }
    }
    __syncthreads();
    if (tid == 0) {
        g_idx[n] = s_bidx;
        atomicAdd(&g_acc[2], __logf(Z) - U / Z);
        float dmin = g_cn[n] - 0.01f * s_bt;
        int b = n >> 10, w = n & 31;
        if (w <= g_q[b]) atomicAdd(&g_acc[0], dmin);
    }
}

// ---------------- column pass: avg_probs from fp16 e (half2), no exps ----------------
__global__ __launch_bounds__(256) void k_colsum() {
    __shared__ float s_s[512][4];
    int tid = threadIdx.x;
    int bx = blockIdx.x;
    int n0 = blockIdx.y * 512;
    int t0 = bx * 4;
    for (int i = tid; i < 512; i += 256) {
        const float* sp = g_scale + (size_t)(n0 + i) * NTILE + t0;
        s_s[i][0] = sp[0]; s_s[i][1] = sp[1]; s_s[i][2] = sp[2]; s_s[i][3] = sp[3];
    }
    __syncthreads();
    int col = bx * 512 + tid * 2;
    int sel = tid >> 6;         // (tid*2)>>7
    const __half2* ep = (const __half2*)(g_e + col);
    float a0 = 0.0f, a1 = 0.0f;
#pragma unroll 8
    for (int i = 0; i < 512; i++) {
        float2 v = __half22float2(ep[(size_t)(n0 + i) * (Ev / 2)]);
        float s = s_s[i][sel];
        a0 = fmaf(v.x, s, a0);
        a1 = fmaf(v.y, s, a1);
    }
    atomicAdd(&g_avgp[col], a0);
    atomicAdd(&g_avgp[col + 1], a1);
}

// ---------------- avg entropy ----------------
__global__ __launch_bounds__(256) void k_avgent() {
    int k = blockIdx.x * 256 + threadIdx.x;
    float ap = g_avgp[k] * (1.0f / (float)Nv);
    float v = -ap * __logf(ap + 1e-5f);
    for (int o = 16; o; o >>= 1) v += __shfl_xor_sync(~0u, v, o);
    __shared__ float ws[8];
    if ((threadIdx.x & 31) == 0) ws[threadIdx.x >> 5] = v;
    __syncthreads();
    if (threadIdx.x == 0) {
        float t = 0.0f;
        for (int w = 0; w < 8; w++) t += ws[w];
        atomicAdd(&g_acc[3], t);
    }
}

// ---------------- dead code rate ----------------
__global__ void k_dead() {
    int j = threadIdx.x;
    int v = g_idx[j];
    int same = 1;
    for (int b = 1; b < Bv; b++) same &= (g_idx[b * 1024 + j] == v);
    for (int o = 16; o; o >>= 1) same += __shfl_xor_sync(~0u, same, o);
    __shared__ int ws[32];
    if ((j & 31) == 0) ws[j >> 5] = same;
    __syncthreads();
    if (j < 32) {
        int t = ws[j];
        for (int o = 16; o; o >>= 1) t += __shfl_xor_sync(~0u, t, o);
        if (j == 0) g_acc[4] = (float)t;
    }
}

// ---------------- z_q output ----------------
__global__ __launch_bounds__(256) void k_output(float* __restrict__ out) {
    __shared__ float sm[Cv][Wv + 1];
    int bh = blockIdx.x, tid = threadIdx.x;
    for (int w = 0; w < 32; ++w) {
        int n = bh * 32 + w;
        int k = g_idx[n];
        float zf = g_zf[(size_t)n * Cv + tid];
        float e  = g_emb[(size_t)k * Cv + tid];
        sm[tid][w] = zf + (e - zf);
    }
    __syncthreads();
    float* op = out + (size_t)(bh >> 5) * Cv * (Hv * Wv) + (size_t)(bh & 31) * Wv;
    for (int it = 0; it < 32; ++it) {
        int l = it * 256 + tid;
        int c = l >> 5, w = l & 31;
        op[(size_t)c * (Hv * Wv) + w] = sm[c][w];
    }
}

// ---------------- scalars + idx ----------------
__global__ void k_finalize(float* __restrict__ out, int out_size) {
    int i = blockIdx.x * blockDim.x + threadIdx.x;
    if (i < Nv && (S0 + 4 + i) < out_size) out[S0 + 4 + i] = (float)g_idx[i];
    if (i == 0 && (S0 + 3) < out_size) {
        float denom = g_acc[1];
        float vq = g_acc[0] / (256.0f * denom);
        out[S0 + 0] = vq;
        out[S0 + 1] = 0.25f * vq;
        float sample = g_acc[2] * (1.0f / (float)Nv);
        out[S0 + 2] = 0.1f * (sample - g_acc[3]);
        out[S0 + 3] = g_acc[4] * (1.0f / 1024.0f);
    }
}

extern "C" void kernel_launch(void* const* d_in, const int* in_sizes, int n_in,
                              void* d_out, int out_size) {
    const float* z   = (const float*)d_in[0];
    const float* emb = (const float*)d_in[1];
    const void*  q   = d_in[2];
    float* out = (float*)d_out;

    cudaFuncSetAttribute(k_mma, cudaFuncAttributeMaxDynamicSharedMemorySize, SM_TOTAL);

    k_init<<<64, 256>>>(q);
    k_norm_z<<<Bv * Hv, 256>>>(z);
    k_norm_emb<<<Ev, 256>>>(emb);
    dim3 gg(Ev / BNBIG, Nv / BM);   // 64 x 128 = 8192 blocks
    k_mma<<<gg, 256, SM_TOTAL>>>();
    k_rowred<<<Nv, 128>>>();
    dim3 gc(Ev / 512, Nv / 512);    // 32 x 32
    k_colsum<<<gc, 256>>>();
    k_avgent<<<Ev / 256, 256>>>();
    k_dead<<<1, 1024>>>();
    k_output<<<Bv * Hv, 256>>>(out);
    k_finalize<<<64, 256>>>(out, out_size);
}

// round 17
// speedup vs baseline: 3.1531x; 1.0067x over previous
#include <cuda_runtime.h>
#include <cuda_bf16.h>
#include <cuda_fp16.h>
#include <math.h>
#include <stdint.h>

// Problem dims (fixed)
#define Bv   16
#define Cv   256
#define Hv   32
#define Wv   32
#define Nv   16384
#define Ev   16384
#define S0   4194304

// GEMM tiling — single fp16 term, A-resident, 4 N-subtiles, 4-stage B pipe
#define KBIG 256
#define BM   128
#define BN   128
#define BNBIG 512
#define NSUB 4
#define BK   32
#define NKT  (KBIG / BK)    // 8
#define NIT  (NSUB * NKT)   // 32
#define ROWA 528
#define ROWB 80
#define A_BYTES (BM * ROWA)          // 67584
#define BSTG (BM * ROWB)             // 10240
#define SMF_OFF (A_BYTES + 4 * BSTG) // 108544
#define SM_TOTAL (SMF_OFF + 6144)    // 114688  (<= 113.5KiB*2 per SM)

#define CAND_EPS 0.15f
#define MAXCAND 32
#define NTILE (Ev / BN)     // 128

// ---------------- device scratch (static, no allocs) ----------------
__device__ float              g_zf[(size_t)Nv * Cv];
__device__ float              g_cn[Nv];
__device__ float              g_emb[(size_t)Ev * Cv];
__device__ float              g_sk[Ev];
__device__ __align__(256) __half g_abig[(size_t)Nv * KBIG];
__device__ __align__(256) __half g_bbig[(size_t)Ev * KBIG];
__device__ __align__(256) __half g_e[(size_t)Nv * Ev];      // exp(t - m_tile), 0.5 GiB
__device__ float4             g_part[(size_t)Nv * NTILE];
__device__ float              g_scale[(size_t)Nv * NTILE];
__device__ int                g_idx[Nv];
__device__ float              g_avgp[Ev];
__device__ int                g_q[Bv];
__device__ float              g_acc[8];

// ---------------- PTX helpers (base-target only) ----------------
__device__ __forceinline__ uint32_t smem_u32(const void* p) {
    uint32_t a;
    asm("{ .reg .u64 t; cvta.to.shared.u64 t, %1; cvt.u32.u64 %0, t; }" : "=r"(a) : "l"(p));
    return a;
}
__device__ __forceinline__ void cp16(uint32_t dst, const void* src) {
    asm volatile("cp.async.cg.shared.global [%0], [%1], 16;" :: "r"(dst), "l"(src) : "memory");
}
__device__ __forceinline__ void cp_commit() {
    asm volatile("cp.async.commit_group;" ::: "memory");
}
template <int N>
__device__ __forceinline__ void cp_wait() {
    asm volatile("cp.async.wait_group %0;" :: "n"(N) : "memory");
}
__device__ __forceinline__ void ldmx4(uint32_t& r0, uint32_t& r1, uint32_t& r2, uint32_t& r3,
                                      uint32_t addr) {
    asm volatile("ldmatrix.sync.aligned.m8n8.x4.shared.b16 {%0,%1,%2,%3}, [%4];"
                 : "=r"(r0), "=r"(r1), "=r"(r2), "=r"(r3) : "r"(addr));
}
__device__ __forceinline__ void hmma(float& c0, float& c1, float& c2, float& c3,
                                     uint32_t a0, uint32_t a1, uint32_t a2, uint32_t a3,
                                     uint32_t b0, uint32_t b1) {
    asm volatile(
        "mma.sync.aligned.m16n8k16.row.col.f32.f16.f16.f32 "
        "{%0,%1,%2,%3}, {%4,%5,%6,%7}, {%8,%9}, {%0,%1,%2,%3};"
        : "+f"(c0), "+f"(c1), "+f"(c2), "+f"(c3)
        : "r"(a0), "r"(a1), "r"(a2), "r"(a3), "r"(b0), "r"(b1));
}

// ---------------- init ----------------
__global__ void k_init(const void* qraw) {
    int i = blockIdx.x * blockDim.x + threadIdx.x;
    if (i < Ev) g_avgp[i] = 0.0f;
    if (i == 0) {
        const unsigned int* w32 = (const unsigned int*)qraw;
        bool is64 = true;
        for (int b = 0; b < 8; b++) if (w32[2 * b + 1] != 0u) is64 = false;
        int s = 0;
        for (int b = 0; b < Bv; b++) {
            int q = is64 ? (int)w32[2 * b] : (int)((const int*)qraw)[b];
            g_q[b] = q;
            s += q + 1;
        }
        for (int j = 0; j < 8; j++) g_acc[j] = 0.0f;
        g_acc[1] = (float)s;
    }
}

// ---------------- normalize z + emit fp16 ----------------
__global__ __launch_bounds__(256) void k_norm_z(const float* __restrict__ z) {
    __shared__ float sm[Cv][Wv + 1];
    __shared__ float sinv[Wv];
    int bh = blockIdx.x;
    int tid = threadIdx.x;
    const float* zp = z + (size_t)(bh >> 5) * Cv * (Hv * Wv) + (size_t)(bh & 31) * Wv;
    for (int it = 0; it < 32; ++it) {
        int l = it * 256 + tid;
        int c = l >> 5, w = l & 31;
        sm[c][w] = zp[(size_t)c * (Hv * Wv) + w];
    }
    __syncthreads();
    int w = tid >> 3, part = tid & 7;
    float s = 0.0f;
    for (int c = part; c < Cv; c += 8) { float v = sm[c][w]; s += v * v; }
    s += __shfl_xor_sync(~0u, s, 1);
    s += __shfl_xor_sync(~0u, s, 2);
    s += __shfl_xor_sync(~0u, s, 4);
    if (part == 0) {
        float inv = 1.0f / fmaxf(sqrtf(s), 1e-12f);
        sinv[w] = inv;
        g_cn[bh * 32 + w] = s * inv * inv;
    }
    __syncthreads();
    for (int w2 = 0; w2 < 32; ++w2) {
        int n = bh * 32 + w2;
        float v = sm[tid][w2] * sinv[w2];
        g_zf[(size_t)n * Cv + tid] = v;
        g_abig[(size_t)n * KBIG + tid] = __float2half(v);
    }
}

// ---------------- normalize embedding + emit fp16 ----------------
__global__ __launch_bounds__(256) void k_norm_emb(const float* __restrict__ e) {
    int k = blockIdx.x, tid = threadIdx.x;
    float v = e[(size_t)k * Cv + tid];
    float s = v * v;
    for (int o = 16; o; o >>= 1) s += __shfl_xor_sync(~0u, s, o);
    __shared__ float ws[8];
    if ((tid & 31) == 0) ws[tid >> 5] = s;
    __syncthreads();
    if (tid < 8) {
        float t = ws[tid];
        for (int o = 4; o; o >>= 1) t += __shfl_xor_sync(0xffu, t, o);
        if (tid == 0) ws[0] = t;
    }
    __syncthreads();
    float tot = ws[0];
    float inv = 1.0f / fmaxf(sqrtf(tot), 1e-12f);
    float vn = v * inv;
    g_emb[(size_t)k * Cv + tid] = vn;
    if (tid == 0) g_sk[k] = tot * inv * inv;
    g_bbig[(size_t)k * KBIG + tid] = __float2half(vn);
}

// ---------------- HMMA GEMM (A-resident, 4 subtiles, 4-stage single-sync) ----------------
__device__ __forceinline__ void load_chunk(uint32_t sbase, int bn0, int it, int tid) {
    int bsub = it >> 3;          // which N-subtile
    int bkt = it & 7;            // which K chunk
    const char* src = (const char*)g_bbig
        + (size_t)(bn0 + bsub * BM) * (KBIG * 2) + bkt * (BK * 2);
    uint32_t base = sbase + A_BYTES + (it & 3) * BSTG;
#pragma unroll
    for (int i = 0; i < 2; i++) {
        int u = tid + i * 256;
        int r = u >> 2, c = (u & 3) * 16;
        cp16(base + r * ROWB + c, src + (size_t)r * (KBIG * 2) + c);
    }
}

__global__ void __launch_bounds__(256, 2) k_mma() {
    extern __shared__ char smem[];
    uint32_t sbase = smem_u32(smem);
    int tid = threadIdx.x, wid = tid >> 5, lane = tid & 31;
    int g = lane >> 2, tig = lane & 3;
    int warpM = wid >> 2, warpN = wid & 3;          // 2 x 4
    int bm = blockIdx.y * BM, bn0 = blockIdx.x * BNBIG;

    const char* Ab = (const char*)g_abig + (size_t)bm * (KBIG * 2);

    // prologue: A tile (group 0), B chunks 0..2 (groups 1..3)
    {
#pragma unroll
        for (int i = 0; i < 16; i++) {
            int u = tid + i * 256;
            int r = u >> 5, c = (u & 31) * 16;
            cp16(sbase + r * ROWA + c, Ab + (size_t)r * (KBIG * 2) + c);
        }
        cp_commit();
        load_chunk(sbase, bn0, 0, tid); cp_commit();
        load_chunk(sbase, bn0, 1, tid); cp_commit();
        load_chunk(sbase, bn0, 2, tid); cp_commit();
    }

    int aoffA = ((((lane >> 3) & 1) * 8 + (lane & 7)) * ROWA) + ((lane >> 4) * 16);
    int boff  = ((((lane >> 4) & 1) * 8 + (lane & 7)) * ROWB) + (((lane >> 3) & 1) * 16);
    uint32_t abase = sbase + (warpM * 64) * ROWA + aoffA;
    uint32_t bwarp = sbase + A_BYTES + (warpN * 32) * ROWB + boff;
    int rbase = warpM * 64 + g;
    float* smf = (float*)(smem + SMF_OFF);

    for (int sub = 0; sub < NSUB; sub++) {
        int bn = bn0 + sub * BM;

        float acc[4][4][4];
#pragma unroll
        for (int mi = 0; mi < 4; mi++)
#pragma unroll
            for (int ni = 0; ni < 4; ni++)
#pragma unroll
                for (int r = 0; r < 4; r++) acc[mi][ni][r] = 0.0f;

        for (int kt = 0; kt < NKT; kt++) {
            int it = sub * NKT + kt;
            cp_wait<2>();           // chunk `it` resident (2 newer groups may be pending)
            __syncthreads();        // single barrier: readers done with stage (it+3)&3
            if (it + 3 < NIT) load_chunk(sbase, bn0, it + 3, tid);
            cp_commit();

            uint32_t bstg = bwarp + (uint32_t)((it & 3) * BSTG);
            uint32_t akt = abase + kt * (BK * 2);
#pragma unroll
            for (int k16 = 0; k16 < 2; k16++) {
                uint32_t koff = k16 * 32;
                uint32_t Ar[4][4], Br[4][2];
#pragma unroll
                for (int mi = 0; mi < 4; mi++)
                    ldmx4(Ar[mi][0], Ar[mi][1], Ar[mi][2], Ar[mi][3],
                          akt + mi * 16 * ROWA + koff);
#pragma unroll
                for (int nip = 0; nip < 2; nip++)
                    ldmx4(Br[2 * nip][0], Br[2 * nip][1], Br[2 * nip + 1][0], Br[2 * nip + 1][1],
                          bstg + nip * 16 * ROWB + koff);
#pragma unroll
                for (int mi = 0; mi < 4; mi++)
#pragma unroll
                    for (int ni = 0; ni < 4; ni++)
                        hmma(acc[mi][ni][0], acc[mi][ni][1], acc[mi][ni][2], acc[mi][ni][3],
                             Ar[mi][0], Ar[mi][1], Ar[mi][2], Ar[mi][3],
                             Br[ni][0], Br[ni][1]);
            }
        }
        __syncthreads();   // mainloop reads done before epilogue reuses smf / next loads race

        // ---- epilogue: t, per-(row,tile) m/Z/U partials, e -> fp16 ----
        int colb = bn + warpN * 32;
        float skv[4][2];
#pragma unroll
        for (int ni = 0; ni < 4; ni++) {
            int c0 = colb + ni * 8 + 2 * tig;
            skv[ni][0] = __ldg(&g_sk[c0]);
            skv[ni][1] = __ldg(&g_sk[c0 + 1]);
        }
        float lm[4][2];
#pragma unroll
        for (int mi = 0; mi < 4; mi++) {
            lm[mi][0] = -3.4e38f; lm[mi][1] = -3.4e38f;
#pragma unroll
            for (int ni = 0; ni < 4; ni++) {
                acc[mi][ni][0] = 200.0f * acc[mi][ni][0] - 100.0f * skv[ni][0];
                acc[mi][ni][1] = 200.0f * acc[mi][ni][1] - 100.0f * skv[ni][1];
                acc[mi][ni][2] = 200.0f * acc[mi][ni][2] - 100.0f * skv[ni][0];
                acc[mi][ni][3] = 200.0f * acc[mi][ni][3] - 100.0f * skv[ni][1];
                lm[mi][0] = fmaxf(lm[mi][0], fmaxf(acc[mi][ni][0], acc[mi][ni][1]));
                lm[mi][1] = fmaxf(lm[mi][1], fmaxf(acc[mi][ni][2], acc[mi][ni][3]));
            }
        }
#pragma unroll
        for (int mi = 0; mi < 4; mi++)
#pragma unroll
            for (int h = 0; h < 2; h++) {
                lm[mi][h] = fmaxf(lm[mi][h], __shfl_xor_sync(~0u, lm[mi][h], 1));
                lm[mi][h] = fmaxf(lm[mi][h], __shfl_xor_sync(~0u, lm[mi][h], 2));
            }
        if (tig == 0) {
#pragma unroll
            for (int mi = 0; mi < 4; mi++)
#pragma unroll
                for (int h = 0; h < 2; h++)
                    smf[(rbase + mi * 16 + h * 8) * 4 + warpN] = lm[mi][h];
        }
        __syncthreads();
        float mt[4][2];
#pragma unroll
        for (int mi = 0; mi < 4; mi++)
#pragma unroll
            for (int h = 0; h < 2; h++) {
                int r4 = (rbase + mi * 16 + h * 8) * 4;
                mt[mi][h] = fmaxf(fmaxf(smf[r4], smf[r4 + 1]), fmaxf(smf[r4 + 2], smf[r4 + 3]));
            }
        float zl[4][2], ul[4][2];
#pragma unroll
        for (int mi = 0; mi < 4; mi++) { zl[mi][0] = zl[mi][1] = 0.0f; ul[mi][0] = ul[mi][1] = 0.0f; }
#pragma unroll
        for (int mi = 0; mi < 4; mi++) {
            size_t r0 = (size_t)(bm + rbase + mi * 16);
            __half* e0 = g_e + r0 * Ev;
            __half* e1 = g_e + (r0 + 8) * Ev;
#pragma unroll
            for (int ni = 0; ni < 4; ni++) {
                int c0 = colb + ni * 8 + 2 * tig;
                float u00 = acc[mi][ni][0] - mt[mi][0];
                float u01 = acc[mi][ni][1] - mt[mi][0];
                float u10 = acc[mi][ni][2] - mt[mi][1];
                float u11 = acc[mi][ni][3] - mt[mi][1];
                float e00 = __expf(u00), e01 = __expf(u01);
                float e10 = __expf(u10), e11 = __expf(u11);
                *(__half2*)(e0 + c0) = __floats2half2_rn(e00, e01);
                *(__half2*)(e1 + c0) = __floats2half2_rn(e10, e11);
                zl[mi][0] += e00 + e01;
                zl[mi][1] += e10 + e11;
                ul[mi][0] += e00 * u00 + e01 * u01;
                ul[mi][1] += e10 * u10 + e11 * u11;
            }
        }
#pragma unroll
        for (int mi = 0; mi < 4; mi++)
#pragma unroll
            for (int h = 0; h < 2; h++) {
                zl[mi][h] += __shfl_xor_sync(~0u, zl[mi][h], 1);
                zl[mi][h] += __shfl_xor_sync(~0u, zl[mi][h], 2);
                ul[mi][h] += __shfl_xor_sync(~0u, ul[mi][h], 1);
                ul[mi][h] += __shfl_xor_sync(~0u, ul[mi][h], 2);
            }
        if (tig == 0) {
#pragma unroll
            for (int mi = 0; mi < 4; mi++)
#pragma unroll
                for (int h = 0; h < 2; h++) {
                    int r = rbase + mi * 16 + h * 8;
                    smf[512 + r * 4 + warpN] = zl[mi][h];
                    smf[1024 + r * 4 + warpN] = ul[mi][h];
                }
        }
        __syncthreads();
        if (warpN == 0 && tig == 0) {
#pragma unroll
            for (int mi = 0; mi < 4; mi++)
#pragma unroll
                for (int h = 0; h < 2; h++) {
                    int r = rbase + mi * 16 + h * 8;
                    float Z = smf[512 + r * 4] + smf[512 + r * 4 + 1] + smf[512 + r * 4 + 2] + smf[512 + r * 4 + 3];
                    float U = smf[1024 + r * 4] + smf[1024 + r * 4 + 1] + smf[1024 + r * 4 + 2] + smf[1024 + r * 4 + 3];
                    g_part[(size_t)(bm + r) * NTILE + (blockIdx.x * NSUB + sub)] =
                        make_float4(mt[mi][h], Z, U, 0.0f);
                }
        }
        __syncthreads();   // smf safe for next subtile
    }
}

// ---------------- row reduce: merge partials, exact refine, scales ----------------
__global__ __launch_bounds__(128) void k_rowred() {
    int n = blockIdx.x, tid = threadIdx.x, wid = tid >> 5, lane = tid & 31;
    __shared__ float wred[4];
    __shared__ int s_cand[MAXCAND];
    __shared__ int s_cnt;
    __shared__ int s_bidx;
    __shared__ float s_bt;
    if (tid == 0) { s_cnt = 0; s_bidx = 0; s_bt = -3.4e38f; }

    float4 p = g_part[(size_t)n * NTILE + tid];
    float mi = p.x, Zi = p.y, Ui = p.z;

    float m = mi;
    for (int o = 16; o; o >>= 1) m = fmaxf(m, __shfl_xor_sync(~0u, m, o));
    if (lane == 0) wred[wid] = m;
    __syncthreads();
    m = fmaxf(fmaxf(wred[0], wred[1]), fmaxf(wred[2], wred[3]));
    __syncthreads();

    float li = __expf(mi - m);
    float Zc = Zi * li;
    float Uc = fmaf(mi - m, Zi, Ui) * li;
    float zs = Zc;
    for (int o = 16; o; o >>= 1) zs += __shfl_xor_sync(~0u, zs, o);
    if (lane == 0) wred[wid] = zs;
    __syncthreads();
    float Z = wred[0] + wred[1] + wred[2] + wred[3];
    __syncthreads();
    float us = Uc;
    for (int o = 16; o; o >>= 1) us += __shfl_xor_sync(~0u, us, o);
    if (lane == 0) wred[wid] = us;
    __syncthreads();
    float U = wred[0] + wred[1] + wred[2] + wred[3];

    g_scale[(size_t)n * NTILE + tid] = li / Z;

    if (mi > m - CAND_EPS) {
        const __half* ep = g_e + (size_t)n * Ev + tid * BN;
        float thr = __expf((m - CAND_EPS) - mi);
        for (int j = 0; j < BN; j++) {
            if (__half2float(ep[j]) > thr) {
                int q = atomicAdd(&s_cnt, 1);
                if (q < MAXCAND) s_cand[q] = tid * BN + j;
            }
        }
    }
    __syncthreads();
    int nc = min(s_cnt, MAXCAND);
    if (tid < 32) {
        float bt = -3.4e38f; int bc = 0x7fffffff;
        if (tid < nc) {
            int k = s_cand[tid];
            const float* ap = g_zf + (size_t)n * Cv;
            const float* bp = g_emb + (size_t)k * Cv;
            float dot = 0.0f;
#pragma unroll 8
            for (int c = 0; c < Cv; c++) dot = fmaf(__ldg(ap + c), __ldg(bp + c), dot);
            bt = 200.0f * dot - 100.0f * __ldg(&g_sk[k]);
            bc = k;
        }
#pragma unroll
        for (int o = 1; o < 32; o <<= 1) {
            float ov = __shfl_xor_sync(~0u, bt, o);
            int   oc = __shfl_xor_sync(~0u, bc, o);
            if (ov > bt || (ov == bt && oc < bc)) { bt = ov; bc = oc; }
        }
        if (tid == 0) { s_bidx = bc; s_bt = bt; }
    }
    __syncthreads();
    if (tid == 0) {
        g_idx[n] = s_bidx;
        atomicAdd(&g_acc[2], __logf(Z) - U / Z);
        float dmin = g_cn[n] - 0.01f * s_bt;
        int b = n >> 10, w = n & 31;
        if (w <= g_q[b]) atomicAdd(&g_acc[0], dmin);
    }
}

// ---------------- column pass: avg_probs from fp16 e (half2), no exps ----------------
__global__ __launch_bounds__(256) void k_colsum() {
    __shared__ float s_s[512][4];
    int tid = threadIdx.x;
    int bx = blockIdx.x;
    int n0 = blockIdx.y * 512;
    int t0 = bx * 4;
    for (int i = tid; i < 512; i += 256) {
        const float* sp = g_scale + (size_t)(n0 + i) * NTILE + t0;
        s_s[i][0] = sp[0]; s_s[i][1] = sp[1]; s_s[i][2] = sp[2]; s_s[i][3] = sp[3];
    }
    __syncthreads();
    int col = bx * 512 + tid * 2;
    int sel = tid >> 6;
    const __half2* ep = (const __half2*)(g_e + col);
    float a0 = 0.0f, a1 = 0.0f;
#pragma unroll 8
    for (int i = 0; i < 512; i++) {
        float2 v = __half22float2(ep[(size_t)(n0 + i) * (Ev / 2)]);
        float s = s_s[i][sel];
        a0 = fmaf(v.x, s, a0);
        a1 = fmaf(v.y, s, a1);
    }
    atomicAdd(&g_avgp[col], a0);
    atomicAdd(&g_avgp[col + 1], a1);
}

// ---------------- avg entropy ----------------
__global__ __launch_bounds__(256) void k_avgent() {
    int k = blockIdx.x * 256 + threadIdx.x;
    float ap = g_avgp[k] * (1.0f / (float)Nv);
    float v = -ap * __logf(ap + 1e-5f);
    for (int o = 16; o; o >>= 1) v += __shfl_xor_sync(~0u, v, o);
    __shared__ float ws[8];
    if ((threadIdx.x & 31) == 0) ws[threadIdx.x >> 5] = v;
    __syncthreads();
    if (threadIdx.x == 0) {
        float t = 0.0f;
        for (int w = 0; w < 8; w++) t += ws[w];
        atomicAdd(&g_acc[3], t);
    }
}

// ---------------- dead code rate ----------------
__global__ void k_dead() {
    int j = threadIdx.x;
    int v = g_idx[j];
    int same = 1;
    for (int b = 1; b < Bv; b++) same &= (g_idx[b * 1024 + j] == v);
    for (int o = 16; o; o >>= 1) same += __shfl_xor_sync(~0u, same, o);
    __shared__ int ws[32];
    if ((j & 31) == 0) ws[j >> 5] = same;
    __syncthreads();
    if (j < 32) {
        int t = ws[j];
        for (int o = 16; o; o >>= 1) t += __shfl_xor_sync(~0u, t, o);
        if (j == 0) g_acc[4] = (float)t;
    }
}

// ---------------- z_q output ----------------
__global__ __launch_bounds__(256) void k_output(float* __restrict__ out) {
    __shared__ float sm[Cv][Wv + 1];
    int bh = blockIdx.x, tid = threadIdx.x;
    for (int w = 0; w < 32; ++w) {
        int n = bh * 32 + w;
        int k = g_idx[n];
        float zf = g_zf[(size_t)n * Cv + tid];
        float e  = g_emb[(size_t)k * Cv + tid];
        sm[tid][w] = zf + (e - zf);
    }
    __syncthreads();
    float* op = out + (size_t)(bh >> 5) * Cv * (Hv * Wv) + (size_t)(bh & 31) * Wv;
    for (int it = 0; it < 32; ++it) {
        int l = it * 256 + tid;
        int c = l >> 5, w = l & 31;
        op[(size_t)c * (Hv * Wv) + w] = sm[c][w];
    }
}

// ---------------- scalars + idx ----------------
__global__ void k_finalize(float* __restrict__ out, int out_size) {
    int i = blockIdx.x * blockDim.x + threadIdx.x;
    if (i < Nv && (S0 + 4 + i) < out_size) out[S0 + 4 + i] = (float)g_idx[i];
    if (i == 0 && (S0 + 3) < out_size) {
        float denom = g_acc[1];
        float vq = g_acc[0] / (256.0f * denom);
        out[S0 + 0] = vq;
        out[S0 + 1] = 0.25f * vq;
        float sample = g_acc[2] * (1.0f / (float)Nv);
        out[S0 + 2] = 0.1f * (sample - g_acc[3]);
        out[S0 + 3] = g_acc[4] * (1.0f / 1024.0f);
    }
}

extern "C" void kernel_launch(void* const* d_in, const int* in_sizes, int n_in,
                              void* d_out, int out_size) {
    const float* z   = (const float*)d_in[0];
    const float* emb = (const float*)d_in[1];
    const void*  q   = d_in[2];
    float* out = (float*)d_out;

    cudaFuncSetAttribute(k_mma, cudaFuncAttributeMaxDynamicSharedMemorySize, SM_TOTAL);

    k_init<<<64, 256>>>(q);
    k_norm_z<<<Bv * Hv, 256>>>(z);
    k_norm_emb<<<Ev, 256>>>(emb);
    dim3 gg(Ev / BNBIG, Nv / BM);   // 32 x 128 = 4096 blocks
    k_mma<<<gg, 256, SM_TOTAL>>>();
    k_rowred<<<Nv, 128>>>();
    dim3 gc(Ev / 512, Nv / 512);
    k_colsum<<<gc, 256>>>();
    k_avgent<<<Ev / 256, 256>>>();
    k_dead<<<1, 1024>>>();
    k_output<<<Bv * Hv, 256>>>(out);
    k_finalize<<<64, 256>>>(out, out_size);
}